// round 14
// baseline (speedup 1.0000x reference)
#include <cuda_runtime.h>
#include <cuda_bf16.h>
#include <cuda_fp16.h>
#include <cstdint>

#define NM   8192
#define DIMM 256
#define NH   8
#define EE   32
#define MB   16
#define NB   512
#define NKEY 32
#define NQKV 768

// ---------------- scratch ----------------------------------------------------
__device__ float g_xp[NM * DIMM];
__device__ __align__(16) __nv_bfloat16 g_xph[NM * DIMM];
__device__ __align__(16) __nv_bfloat16 g_xpl[NM * DIMM];
__device__ float g_wq[256 * DIMM];                 // permuted fp32 Q weights (row h*32+e)
__device__ float g_wkf[256 * DIMM];                // permuted fp32 K weights (row h*32+e)
__device__ __align__(16) __nv_bfloat16 g_wvkh[512 * DIMM];  // rows 0-255 V, 256-511 K
__device__ __align__(16) __nv_bfloat16 g_wvkl[512 * DIMM];
__device__ __align__(16) __nv_bfloat16 g_wph[DIMM * DIMM];
__device__ __align__(16) __nv_bfloat16 g_wpl[DIMM * DIMM];
__device__ __align__(16) __nv_bfloat16 g_aoh[NM * DIMM];
__device__ __align__(16) __nv_bfloat16 g_aol[NM * DIMM];
__device__ float g_q[NH * NM * EE];
__device__ __align__(16) __half g_kh[NH * NM * EE];  // fp16 K (k5 logits)
__device__ __align__(16) __half g_vh[NH * NM * EE];  // fp16 V
__device__ float g_xpm[NB * DIMM];                   // per-ball mean of xp
__device__ int   g_idx[NH * NM * 2];
// 3-way bf16 splits for the selection GEMM (exact to ~2^-25)
__device__ __align__(16) __nv_bfloat16 g_q1[NH * NM * EE];
__device__ __align__(16) __nv_bfloat16 g_q2[NH * NM * EE];
__device__ __align__(16) __nv_bfloat16 g_q3[NH * NM * EE];
__device__ __align__(16) __nv_bfloat16 g_km1[NH * NB * EE];
__device__ __align__(16) __nv_bfloat16 g_km2[NH * NB * EE];
__device__ __align__(16) __nv_bfloat16 g_km3[NH * NB * EE];

// ---------------- packed f32x2 helpers ----------------------------------------
typedef unsigned long long ull;
__device__ __forceinline__ ull pack2(float x, float y) {
    ull r; asm("mov.b64 %0, {%1, %2};" : "=l"(r) : "f"(x), "f"(y)); return r;
}
__device__ __forceinline__ ull fma2(ull a, ull b, ull c) {
    ull d; asm("fma.rn.f32x2 %0, %1, %2, %3;" : "=l"(d) : "l"(a), "l"(b), "l"(c));
    return d;
}
__device__ __forceinline__ void unpack2(ull v, float& lo, float& hi) {
    asm("mov.b64 {%0, %1}, %2;" : "=f"(lo), "=f"(hi) : "l"(v));
}

// ---------------- mma.sync helpers ---------------------------------------------
__device__ __forceinline__ uint32_t smem_u32(const void* p) {
    uint32_t a;
    asm("{ .reg .u64 t; cvta.to.shared.u64 t, %1; cvt.u32.u64 %0, t; }" : "=r"(a) : "l"(p));
    return a;
}
__device__ __forceinline__ uint32_t swz_addr(uint32_t base, int r, int cb) {
    uint32_t off = (uint32_t)(r * 128 + cb);
    off ^= (off >> 3) & 0x70;
    return base + off;
}
__device__ __forceinline__ void ldsm4(uint32_t& r0, uint32_t& r1, uint32_t& r2,
                                      uint32_t& r3, uint32_t addr) {
    asm volatile("ldmatrix.sync.aligned.m8n8.x4.shared.b16 {%0,%1,%2,%3}, [%4];"
                 : "=r"(r0), "=r"(r1), "=r"(r2), "=r"(r3) : "r"(addr));
}
__device__ __forceinline__ void mma16816(float* d, const uint32_t* a,
                                         uint32_t b0, uint32_t b1) {
    asm volatile(
        "mma.sync.aligned.m16n8k16.row.col.f32.bf16.bf16.f32 "
        "{%0,%1,%2,%3}, {%4,%5,%6,%7}, {%8,%9}, {%0,%1,%2,%3};"
        : "+f"(d[0]), "+f"(d[1]), "+f"(d[2]), "+f"(d[3])
        : "r"(a[0]), "r"(a[1]), "r"(a[2]), "r"(a[3]), "r"(b0), "r"(b1));
}
__device__ __forceinline__ void cpasync16(uint32_t dst, const void* src) {
    asm volatile("cp.async.cg.shared.global [%0], [%1], 16;" :: "r"(dst), "l"(src));
}

// ---------------- k01: weight permutation/splits + PE add + xp ball means ----------
__global__ void k01(const float* __restrict__ x, const float* __restrict__ pos,
                    const float* __restrict__ Wpe, const float* __restrict__ bpe,
                    const float* __restrict__ Wq, const float* __restrict__ Wp) {
    __shared__ float rel[MB][3];
    int tid = threadIdx.x;
    if (blockIdx.x < 1024) {
        int i = blockIdx.x * 256 + tid;
        if (i < NQKV * DIMM) {
            int c = i >> 8, d = i & 255;
            int h = c / 96, t = c % 96, e = t / 3, s = t - e * 3;
            float v = Wq[i];
            int row = h * 32 + e;
            if (s == 0) {
                g_wq[row * DIMM + d] = v;
            } else {
                __nv_bfloat16 hh = __float2bfloat16(v);
                int brow = (s == 2) ? row : 256 + row;   // V rows 0-255, K rows 256-511
                g_wvkh[brow * DIMM + d] = hh;
                g_wvkl[brow * DIMM + d] = __float2bfloat16(v - __bfloat162float(hh));
                if (s == 1) g_wkf[row * DIMM + d] = v;
            }
        } else {
            int j = i - NQKV * DIMM;
            float v = Wp[j];
            __nv_bfloat16 hh = __float2bfloat16(v);
            g_wph[j] = hh;
            g_wpl[j] = __float2bfloat16(v - __bfloat162float(hh));
        }
        return;
    }
    int ball = blockIdx.x - 1024;
    if (tid < 3) {
        float s = 0.f;
        for (int m = 0; m < MB; m++) s += pos[(ball * MB + m) * 3 + tid];
        float mean = s * (1.f / MB);
        for (int m = 0; m < MB; m++)
            rel[m][tid] = pos[(ball * MB + m) * 3 + tid] - mean;
    }
    __syncthreads();
    int d = tid;
    float w0 = Wpe[d * 3 + 0], w1 = Wpe[d * 3 + 1], w2 = Wpe[d * 3 + 2];
    float b  = bpe[d];
    float xs = 0.f;
    #pragma unroll
    for (int m = 0; m < MB; m++) {
        int t = ball * MB + m;
        float v = x[t * DIMM + d]
                + rel[m][0] * w0 + rel[m][1] * w1 + rel[m][2] * w2 + b;
        g_xp[t * DIMM + d] = v;
        xs += v;
        __nv_bfloat16 h = __float2bfloat16(v);
        g_xph[t * DIMM + d] = h;
        g_xpl[t * DIMM + d] = __float2bfloat16(v - __bfloat162float(h));
    }
    g_xpm[ball * DIMM + d] = xs * (1.f / MB);
}

// ---------------- fp32 f32x2 GEMM-NT for Q: 64x128 tiles, 256 CTAs @2/SM ----------
__global__ void __launch_bounds__(256, 2)
k2_q(const float* __restrict__ bias) {
    __shared__ float As[2][16 * 68];
    __shared__ float Bs[2][16 * 132];
    int tid = threadIdx.x;
    int tx = tid & 15, ty = tid >> 4;
    int row0 = blockIdx.x * 64, col0 = blockIdx.y * 128;

    int ra  = tid & 63;
    int ka4 = (tid >> 6) * 4;
    int rb  = tid & 127;
    int kb8 = (tid >> 7) * 8;

    const float* Ap = g_xp + (row0 + ra) * DIMM + ka4;
    const float* Bp = g_wq + (col0 + rb) * DIMM + kb8;

    float4 pa  = *(const float4*)(Ap);
    float4 pb0 = *(const float4*)(Bp);
    float4 pb1 = *(const float4*)(Bp + 4);

    ull accp[4][4] = {};
    #pragma unroll 2
    for (int c = 0; c < 16; c++) {
        float* A = As[c & 1];
        float* B = Bs[c & 1];
        A[(ka4 + 0) * 68 + ra] = pa.x;
        A[(ka4 + 1) * 68 + ra] = pa.y;
        A[(ka4 + 2) * 68 + ra] = pa.z;
        A[(ka4 + 3) * 68 + ra] = pa.w;
        B[(kb8 + 0) * 132 + rb] = pb0.x; B[(kb8 + 1) * 132 + rb] = pb0.y;
        B[(kb8 + 2) * 132 + rb] = pb0.z; B[(kb8 + 3) * 132 + rb] = pb0.w;
        B[(kb8 + 4) * 132 + rb] = pb1.x; B[(kb8 + 5) * 132 + rb] = pb1.y;
        B[(kb8 + 6) * 132 + rb] = pb1.z; B[(kb8 + 7) * 132 + rb] = pb1.w;
        __syncthreads();
        if (c < 15) {
            int k0n = (c + 1) * 16;
            pa  = *(const float4*)(Ap + k0n);
            pb0 = *(const float4*)(Bp + k0n);
            pb1 = *(const float4*)(Bp + k0n + 4);
        }
        #pragma unroll
        for (int kk = 0; kk < 16; kk++) {
            float4 a  = *(const float4*)(A + kk * 68 + ty * 4);
            float4 b0 = *(const float4*)(B + kk * 132 + tx * 4);
            float4 b1 = *(const float4*)(B + kk * 132 + 64 + tx * 4);
            ull bp[4] = {pack2(b0.x, b0.y), pack2(b0.z, b0.w),
                         pack2(b1.x, b1.y), pack2(b1.z, b1.w)};
            float av[4] = {a.x, a.y, a.z, a.w};
            #pragma unroll
            for (int i = 0; i < 4; i++) {
                ull ap = pack2(av[i], av[i]);
                #pragma unroll
                for (int j = 0; j < 4; j++) accp[i][j] = fma2(ap, bp[j], accp[i][j]);
            }
        }
        __syncthreads();
    }
    float acc[4][8];
    #pragma unroll
    for (int i = 0; i < 4; i++)
        #pragma unroll
        for (int j = 0; j < 4; j++)
            unpack2(accp[i][j], acc[i][2 * j], acc[i][2 * j + 1]);
    #pragma unroll
    for (int i = 0; i < 4; i++) {
        int rr = row0 + ty * 4 + i;
        #pragma unroll
        for (int j = 0; j < 8; j++) {
            int cp = col0 + ((j < 4) ? tx * 4 + j : 64 + tx * 4 + j - 4);
            int h = cp >> 5, e = cp & 31;
            float v = acc[i][j] + bias[h * 96 + e * 3];
            int qi = (h * NM + rr) * EE + e;
            g_q[qi] = v;
            __nv_bfloat16 b1 = __float2bfloat16(v);
            float f1 = __bfloat162float(b1);
            __nv_bfloat16 b2 = __float2bfloat16(v - f1);
            float f2 = __bfloat162float(b2);
            __nv_bfloat16 b3 = __float2bfloat16(v - f1 - f2);
            g_q1[qi] = b1; g_q2[qi] = b2; g_q3[qi] = b3;
        }
    }
}

// ---------------- split-bf16 HMMA GEMM-NT, 64x128 tile, cp.async pipelined ---------
// MODE 0: A=g_xph/l (64 rows), B=g_wvkh/l (N=512: V cols 0-255, K cols 256-511).
// MODE 1: A=g_aoh/l, B=g_wph/l (N=256) -> out.
// stage layout: Ah @0 (8KB), Al @8KB, Bh @16KB (16KB), Bl @32KB; stage = 48KB.
template<int MODE>
__device__ __forceinline__ void issue_chunk(uint32_t stage, int row0, int col0,
                                            int k0, int tid) {
    const __nv_bfloat16* Ah = (MODE == 0) ? g_xph : g_aoh;
    const __nv_bfloat16* Al = (MODE == 0) ? g_xpl : g_aol;
    const __nv_bfloat16* Bh = (MODE == 0) ? g_wvkh : g_wph;
    const __nv_bfloat16* Bl = (MODE == 0) ? g_wvkl : g_wpl;
    // A splits: 64 rows x 8 units = 512 units each
    #pragma unroll
    for (int b = 0; b < 2; b++) {
        const __nv_bfloat16* src = (b == 0) ? Ah : Al;
        #pragma unroll
        for (int l = 0; l < 2; l++) {
            int u = tid + l * 256;
            int r = u >> 3, cc = u & 7;
            const void* g = src + (row0 + r) * DIMM + k0 + cc * 8;
            uint32_t off = (uint32_t)(r * 128 + cc * 16);
            off ^= (off >> 3) & 0x70;
            cpasync16(stage + b * 8192 + off, g);
        }
    }
    // B splits: 128 rows x 8 units = 1024 units each
    #pragma unroll
    for (int b = 0; b < 2; b++) {
        const __nv_bfloat16* src = (b == 0) ? Bh : Bl;
        #pragma unroll
        for (int l = 0; l < 4; l++) {
            int u = tid + l * 256;
            int r = u >> 3, cc = u & 7;
            const void* g = src + (col0 + r) * DIMM + k0 + cc * 8;
            uint32_t off = (uint32_t)(r * 128 + cc * 16);
            off ^= (off >> 3) & 0x70;
            cpasync16(stage + 16384 + b * 16384 + off, g);
        }
    }
    asm volatile("cp.async.commit_group;" ::: "memory");
}

#define GSTAGE 49152

template<int MODE>
__global__ void __launch_bounds__(256, 2)
gemm_mma(const float* __restrict__ bias, float* __restrict__ out) {
    extern __shared__ char dsm_raw[];
    int tid = threadIdx.x;
    int wid = tid >> 5, lane = tid & 31;
    int row0 = blockIdx.x * 64, col0 = blockIdx.y * 128;
    int warp_m = (wid & 1) * 32;
    int warp_n = (wid >> 1) * 32;

    uint32_t raw = smem_u32(dsm_raw);
    uint32_t sbase = (raw + 1023u) & ~1023u;

    float acc[2][4][4] = {};
    int lr = lane & 7;
    int g  = lane >> 3;

    issue_chunk<MODE>(sbase, row0, col0, 0, tid);

    for (int chunk = 0; chunk < 4; chunk++) {
        if (chunk < 3)
            issue_chunk<MODE>(sbase + ((chunk + 1) & 1) * GSTAGE,
                              row0, col0, (chunk + 1) * 64, tid);
        if (chunk < 3)
            asm volatile("cp.async.wait_group 1;" ::: "memory");
        else
            asm volatile("cp.async.wait_group 0;" ::: "memory");
        __syncthreads();

        uint32_t st = sbase + (chunk & 1) * GSTAGE;
        uint32_t aBuf[2] = {st, st + 8192};
        uint32_t bBuf[2] = {st + 16384, st + 32768};

        #pragma unroll
        for (int pass = 0; pass < 3; pass++) {
            uint32_t abase = aBuf[(pass == 2) ? 1 : 0];
            uint32_t bbase = bBuf[(pass == 1) ? 1 : 0];
            #pragma unroll
            for (int ks = 0; ks < 4; ks++) {
                uint32_t af[2][4];
                #pragma unroll
                for (int mi = 0; mi < 2; mi++) {
                    int row = warp_m + mi * 16 + ((g & 1) << 3) + lr;
                    int cb  = ks * 32 + ((g >> 1) << 4);
                    ldsm4(af[mi][0], af[mi][1], af[mi][2], af[mi][3],
                          swz_addr(abase, row, cb));
                }
                uint32_t bf[4][2];
                #pragma unroll
                for (int p = 0; p < 2; p++) {
                    int n  = warp_n + p * 16 + ((g >> 1) << 3) + lr;
                    int cb = ks * 32 + ((g & 1) << 4);
                    uint32_t r0, r1, r2, r3;
                    ldsm4(r0, r1, r2, r3, swz_addr(bbase, n, cb));
                    bf[p * 2 + 0][0] = r0; bf[p * 2 + 0][1] = r1;
                    bf[p * 2 + 1][0] = r2; bf[p * 2 + 1][1] = r3;
                }
                #pragma unroll
                for (int mi = 0; mi < 2; mi++)
                    #pragma unroll
                    for (int nj = 0; nj < 4; nj++)
                        mma16816(acc[mi][nj], af[mi], bf[nj][0], bf[nj][1]);
            }
        }
        __syncthreads();
    }

    int erow = lane >> 2;
    int ecol = (lane & 3) * 2;
    #pragma unroll
    for (int mi = 0; mi < 2; mi++) {
        #pragma unroll
        for (int nj = 0; nj < 4; nj++) {
            #pragma unroll
            for (int half = 0; half < 2; half++) {
                int r = row0 + warp_m + mi * 16 + erow + half * 8;
                #pragma unroll
                for (int rg = 0; rg < 2; rg++) {
                    int cp = col0 + warp_n + nj * 8 + ecol + rg;
                    float a = acc[mi][nj][half * 2 + rg];
                    if (MODE == 0) {
                        if (cp < 256) {   // V
                            int h = cp >> 5, e = cp & 31;
                            float v = a + bias[h * 96 + e * 3 + 2];
                            g_vh[(h * NM + r) * EE + e] = __float2half(v);
                        } else {          // K
                            int m = cp - 256;
                            int h = m >> 5, e = m & 31;
                            float v = a + bias[h * 96 + e * 3 + 1];
                            g_kh[(h * NM + r) * EE + e] = __float2half(v);
                        }
                    } else {
                        out[r * DIMM + cp] = a + bias[cp];
                    }
                }
            }
        }
    }
}

// ---------------- kmg: kmean = xpm @ Wk^T + bk, fused 3-way split --------------------
__global__ void __launch_bounds__(256)
kmg(const float* __restrict__ bias) {
    __shared__ float xm[8 * DIMM];
    int b0 = blockIdx.x * 8;
    int tid = threadIdx.x;
    #pragma unroll
    for (int i = 0; i < 8; i++)
        xm[i * DIMM + tid] = g_xpm[(b0 + i) * DIMM + tid];
    __syncthreads();

    int h = tid >> 5, e = tid & 31;
    const float4* w = (const float4*)(g_wkf + tid * DIMM);
    float acc[8] = {};
    #pragma unroll 8
    for (int k4i = 0; k4i < 64; k4i++) {
        float4 wv = w[k4i];
        #pragma unroll
        for (int i = 0; i < 8; i++) {
            const float4 xv = *(const float4*)(xm + i * DIMM + k4i * 4);
            acc[i] += wv.x * xv.x + wv.y * xv.y + wv.z * xv.z + wv.w * xv.w;
        }
    }
    float bk = bias[h * 96 + e * 3 + 1];
    #pragma unroll
    for (int i = 0; i < 8; i++) {
        float v = acc[i] + bk;
        int t = (h * NB + b0 + i) * EE + e;
        __nv_bfloat16 b1 = __float2bfloat16(v);
        float f1 = __bfloat162float(b1);
        __nv_bfloat16 b2 = __float2bfloat16(v - f1);
        float f2 = __bfloat162float(b2);
        __nv_bfloat16 b3 = __float2bfloat16(v - f1 - f2);
        g_km1[t] = b1; g_km2[t] = b2; g_km3[t] = b3;
    }
}

// ---------------- k4: sim via HMMA, 32 tok/warp, 4 chains, B prefetch ---------------
__device__ __forceinline__ void k4_load_b(uint32_t bfr[3][2][2], int h, int ball0,
                                          int mrow, int ep) {
    const __nv_bfloat16* ms[3] = {g_km1, g_km2, g_km3};
    #pragma unroll
    for (int s = 0; s < 3; s++) {
        const __nv_bfloat16* m = ms[s] + (h * NB + ball0 + mrow) * EE;
        #pragma unroll
        for (int kk = 0; kk < 2; kk++) {
            int e = kk * 16 + ep;
            bfr[s][kk][0] = *(const uint32_t*)(m + e);
            bfr[s][kk][1] = *(const uint32_t*)(m + e + 8);
        }
    }
}

__device__ __forceinline__ void top2_merge(float& v1, float& v2, int& i1, int& i2,
                                           float s, int c) {
    if (s > v1) { v2 = v1; i2 = i1; v1 = s; i1 = c; }
    else if (s > v2) { v2 = s; i2 = c; }
}

__global__ void __launch_bounds__(256, 2)
k4_top2() {
    int h = blockIdx.y;
    int tid = threadIdx.x;
    int wid = tid >> 5, lane = tid & 31;
    int tokw = blockIdx.x * 256 + wid * 32;
    int mrow = lane >> 2;
    int ep   = (lane & 3) * 2;

    const __nv_bfloat16* qs[3] = {g_q1, g_q2, g_q3};

    uint32_t afr[2][3][2][4];
    #pragma unroll
    for (int m = 0; m < 2; m++) {
        #pragma unroll
        for (int s = 0; s < 3; s++) {
            const __nv_bfloat16* q = qs[s] + (h * NM + tokw + m * 16) * EE;
            #pragma unroll
            for (int kk = 0; kk < 2; kk++) {
                int e = kk * 16 + ep;
                afr[m][s][kk][0] = *(const uint32_t*)(q + (mrow    ) * EE + e);
                afr[m][s][kk][1] = *(const uint32_t*)(q + (mrow + 8) * EE + e);
                afr[m][s][kk][2] = *(const uint32_t*)(q + (mrow    ) * EE + e + 8);
                afr[m][s][kk][3] = *(const uint32_t*)(q + (mrow + 8) * EE + e + 8);
            }
        }
    }

    float v1[4], v2[4];
    int   i1[4], i2[4];
    #pragma unroll
    for (int r = 0; r < 4; r++) { v1[r] = -1e30f; v2[r] = -1e30f; i1[r] = 0; i2[r] = 0; }

    uint32_t bf[2][3][2][2];
    k4_load_b(bf[0], h, 0, mrow, ep);

    #pragma unroll 2
    for (int grp = 0; grp < 64; grp++) {
        int cur = grp & 1;
        int ball0 = grp * 8;
        if (grp < 63)
            k4_load_b(bf[cur ^ 1], h, ball0 + 8, mrow, ep);

        float ac[4][4] = {};
        #pragma unroll
        for (int kk = 0; kk < 2; kk++) {
            uint32_t b00 = bf[cur][0][kk][0], b01 = bf[cur][0][kk][1];
            uint32_t b10 = bf[cur][1][kk][0], b11 = bf[cur][1][kk][1];
            uint32_t b20 = bf[cur][2][kk][0], b21 = bf[cur][2][kk][1];
            mma16816(ac[0], afr[0][0][kk], b00, b01);
            mma16816(ac[2], afr[1][0][kk], b00, b01);
            mma16816(ac[1], afr[0][0][kk], b10, b11);
            mma16816(ac[3], afr[1][0][kk], b10, b11);
            mma16816(ac[0], afr[0][1][kk], b00, b01);
            mma16816(ac[2], afr[1][1][kk], b00, b01);
            mma16816(ac[1], afr[0][1][kk], b10, b11);
            mma16816(ac[3], afr[1][1][kk], b10, b11);
            mma16816(ac[0], afr[0][0][kk], b20, b21);
            mma16816(ac[2], afr[1][0][kk], b20, b21);
            mma16816(ac[1], afr[0][2][kk], b00, b01);
            mma16816(ac[3], afr[1][2][kk], b00, b01);
        }

        int c0 = ball0 + ep, c1 = c0 + 1;
        #pragma unroll
        for (int m = 0; m < 2; m++) {
            float s0 = ac[2 * m][0] + ac[2 * m + 1][0];
            float s1 = ac[2 * m][1] + ac[2 * m + 1][1];
            float s2 = ac[2 * m][2] + ac[2 * m + 1][2];
            float s3 = ac[2 * m][3] + ac[2 * m + 1][3];
            int ra = m * 2, rb = m * 2 + 1;
            top2_merge(v1[ra], v2[ra], i1[ra], i2[ra], s0, c0);
            top2_merge(v1[ra], v2[ra], i1[ra], i2[ra], s1, c1);
            top2_merge(v1[rb], v2[rb], i1[rb], i2[rb], s2, c0);
            top2_merge(v1[rb], v2[rb], i1[rb], i2[rb], s3, c1);
        }
    }

    #pragma unroll
    for (int r = 0; r < 4; r++) {
        float a1 = v1[r], a2 = v2[r];
        int   b1 = i1[r], b2 = i2[r];
        #pragma unroll
        for (int d = 1; d < 4; d <<= 1) {
            float o1 = __shfl_xor_sync(0xffffffffu, a1, d);
            float o2 = __shfl_xor_sync(0xffffffffu, a2, d);
            int  oi1 = __shfl_xor_sync(0xffffffffu, b1, d);
            int  oi2 = __shfl_xor_sync(0xffffffffu, b2, d);
            if (o1 > a1) {
                if (a1 > o2) { a2 = a1; b2 = b1; } else { a2 = o2; b2 = oi2; }
                a1 = o1; b1 = oi1;
            } else if (o1 > a2) { a2 = o1; b2 = oi1; }
        }
        if ((lane & 3) == 0) {
            int tok = h * NM + tokw + (r >> 1) * 16 + (r & 1) * 8 + mrow;
            g_idx[tok * 2 + 0] = b1;
            g_idx[tok * 2 + 1] = b2;
        }
    }
}

// ---------------- k5: gathered 32-key attention (fp16 K,V) + bf16 split out ---------
__global__ void k5_attn() {
    int warp = (blockIdx.x * blockDim.x + threadIdx.x) >> 5;
    int lane = threadIdx.x & 31;
    int h = warp >> 13;
    int tok = warp & (NM - 1);
    int b0 = g_idx[warp * 2 + 0];
    int b1 = g_idx[warp * 2 + 1];

    int ball = (lane < 16) ? b0 : b1;
    int ktok = ball * MB + (lane & 15);
    const uint4*  kr4  = (const uint4*)(g_kh + (h * NM + ktok) * EE);
    const float4* qrow = (const float4*)(g_q + (h * NM + tok) * EE);
    float logit = 0.f;
    #pragma unroll
    for (int i = 0; i < 4; i++) {
        uint4 u = kr4[i];
        float4 qa = qrow[2 * i], qb = qrow[2 * i + 1];
        float2 k0 = __half22float2(*(__half2*)&u.x);
        float2 k1 = __half22float2(*(__half2*)&u.y);
        float2 k2 = __half22float2(*(__half2*)&u.z);
        float2 k3 = __half22float2(*(__half2*)&u.w);
        logit += qa.x * k0.x + qa.y * k0.y + qa.z * k1.x + qa.w * k1.y
               + qb.x * k2.x + qb.y * k2.y + qb.z * k3.x + qb.w * k3.y;
    }
    logit *= 0.17677669529663688f;

    float m = logit;
    #pragma unroll
    for (int off = 16; off > 0; off >>= 1)
        m = fmaxf(m, __shfl_xor_sync(0xffffffffu, m, off));
    float p = __expf(logit - m);
    float s = p;
    #pragma unroll
    for (int off = 16; off > 0; off >>= 1)
        s += __shfl_xor_sync(0xffffffffu, s, off);
    float attn = p / s;

    float out = 0.f;
    #pragma unroll
    for (int kk = 0; kk < NKEY; kk++) {
        float a = __shfl_sync(0xffffffffu, attn, kk);
        int kt = ((kk < 16) ? b0 : b1) * MB + (kk & 15);
        out += a * __half2float(g_vh[(h * NM + kt) * EE + lane]);
    }
    int oi = tok * DIMM + h * EE + lane;
    __nv_bfloat16 hi = __float2bfloat16(out);
    g_aoh[oi] = hi;
    g_aol[oi] = __float2bfloat16(out - __bfloat162float(hi));
}

// ---------------- launch --------------------------------------------------------------
extern "C" void kernel_launch(void* const* d_in, const int* in_sizes, int n_in,
                              void* d_out, int out_size) {
    const float* x     = (const float*)d_in[0];
    const float* pos   = (const float*)d_in[1];
    const float* Wqkv  = (const float*)d_in[2];
    const float* bqkv  = (const float*)d_in[3];
    const float* Wpe   = (const float*)d_in[4];
    const float* bpe   = (const float*)d_in[5];
    const float* Wproj = (const float*)d_in[6];
    const float* bproj = (const float*)d_in[7];
    float* out = (float*)d_out;

    const int DSMEM = 2 * GSTAGE + 1024;   // 99328
    cudaFuncSetAttribute(gemm_mma<0>, cudaFuncAttributeMaxDynamicSharedMemorySize, DSMEM);
    cudaFuncSetAttribute(gemm_mma<1>, cudaFuncAttributeMaxDynamicSharedMemorySize, DSMEM);

    k01<<<1024 + NB, 256>>>(x, pos, Wpe, bpe, Wqkv, Wproj);
    k2_q<<<dim3(NM / 64, 2), 256>>>(bqkv);
    gemm_mma<0><<<dim3(NM / 64, 4), 256, DSMEM>>>(bqkv, nullptr);
    kmg<<<NB / 8, 256>>>(bqkv);
    k4_top2<<<dim3(NM / 256, NH), 256>>>();
    k5_attn<<<(NH * NM * 32) / 256, 256>>>();
    gemm_mma<1><<<dim3(NM / 64, 2), 256, DSMEM>>>(bproj, out);
}

// round 15
// speedup vs baseline: 1.0097x; 1.0097x over previous
#include <cuda_runtime.h>
#include <cuda_bf16.h>
#include <cuda_fp16.h>
#include <cstdint>

#define NM   8192
#define DIMM 256
#define NH   8
#define EE   32
#define MB   16
#define NB   512
#define NKEY 32
#define NQKV 768

// ---------------- scratch ----------------------------------------------------
__device__ float g_xp[NM * DIMM];
__device__ __align__(16) __nv_bfloat16 g_xph[NM * DIMM];
__device__ __align__(16) __nv_bfloat16 g_xpl[NM * DIMM];
__device__ float g_wq[256 * DIMM];                  // permuted fp32 Q weights
__device__ float g_wkt[DIMM * 256];                 // transposed fp32 K weights [d][col]
__device__ __align__(16) __nv_bfloat16 g_wvkh[512 * DIMM];  // rows 0-255 V, 256-511 K
__device__ __align__(16) __nv_bfloat16 g_wvkl[512 * DIMM];
__device__ __align__(16) __nv_bfloat16 g_wph[DIMM * DIMM];
__device__ __align__(16) __nv_bfloat16 g_wpl[DIMM * DIMM];
__device__ __align__(16) __nv_bfloat16 g_aoh[NM * DIMM];
__device__ __align__(16) __nv_bfloat16 g_aol[NM * DIMM];
__device__ float g_q[NH * NM * EE];
__device__ __align__(16) __half g_kh[NH * NM * EE];  // fp16 K (k5 logits)
__device__ __align__(16) __half g_vh[NH * NM * EE];  // fp16 V
__device__ float g_xpm[NB * DIMM];                   // per-ball mean of xp
__device__ int   g_idx[NH * NM * 2];
// 3-way bf16 splits for the selection GEMM (exact to ~2^-25)
__device__ __align__(16) __nv_bfloat16 g_q1[NH * NM * EE];
__device__ __align__(16) __nv_bfloat16 g_q2[NH * NM * EE];
__device__ __align__(16) __nv_bfloat16 g_q3[NH * NM * EE];
__device__ __align__(16) __nv_bfloat16 g_km1[NH * NB * EE];
__device__ __align__(16) __nv_bfloat16 g_km2[NH * NB * EE];
__device__ __align__(16) __nv_bfloat16 g_km3[NH * NB * EE];

// ---------------- packed f32x2 helpers ----------------------------------------
typedef unsigned long long ull;
__device__ __forceinline__ ull pack2(float x, float y) {
    ull r; asm("mov.b64 %0, {%1, %2};" : "=l"(r) : "f"(x), "f"(y)); return r;
}
__device__ __forceinline__ ull fma2(ull a, ull b, ull c) {
    ull d; asm("fma.rn.f32x2 %0, %1, %2, %3;" : "=l"(d) : "l"(a), "l"(b), "l"(c));
    return d;
}
__device__ __forceinline__ void unpack2(ull v, float& lo, float& hi) {
    asm("mov.b64 {%0, %1}, %2;" : "=f"(lo), "=f"(hi) : "l"(v));
}

// ---------------- mma.sync helpers ---------------------------------------------
__device__ __forceinline__ uint32_t smem_u32(const void* p) {
    uint32_t a;
    asm("{ .reg .u64 t; cvta.to.shared.u64 t, %1; cvt.u32.u64 %0, t; }" : "=r"(a) : "l"(p));
    return a;
}
__device__ __forceinline__ uint32_t swz_addr(uint32_t base, int r, int cb) {
    uint32_t off = (uint32_t)(r * 128 + cb);
    off ^= (off >> 3) & 0x70;
    return base + off;
}
__device__ __forceinline__ void ldsm4(uint32_t& r0, uint32_t& r1, uint32_t& r2,
                                      uint32_t& r3, uint32_t addr) {
    asm volatile("ldmatrix.sync.aligned.m8n8.x4.shared.b16 {%0,%1,%2,%3}, [%4];"
                 : "=r"(r0), "=r"(r1), "=r"(r2), "=r"(r3) : "r"(addr));
}
__device__ __forceinline__ void mma16816(float* d, const uint32_t* a,
                                         uint32_t b0, uint32_t b1) {
    asm volatile(
        "mma.sync.aligned.m16n8k16.row.col.f32.bf16.bf16.f32 "
        "{%0,%1,%2,%3}, {%4,%5,%6,%7}, {%8,%9}, {%0,%1,%2,%3};"
        : "+f"(d[0]), "+f"(d[1]), "+f"(d[2]), "+f"(d[3])
        : "r"(a[0]), "r"(a[1]), "r"(a[2]), "r"(a[3]), "r"(b0), "r"(b1));
}
__device__ __forceinline__ void cpasync16(uint32_t dst, const void* src) {
    asm volatile("cp.async.cg.shared.global [%0], [%1], 16;" :: "r"(dst), "l"(src));
}

// ---------------- k01: weight permutation/splits + PE add + xp ball means ----------
__global__ void k01(const float* __restrict__ x, const float* __restrict__ pos,
                    const float* __restrict__ Wpe, const float* __restrict__ bpe,
                    const float* __restrict__ Wq, const float* __restrict__ Wp) {
    __shared__ float rel[MB][3];
    int tid = threadIdx.x;
    if (blockIdx.x < 1024) {
        int i = blockIdx.x * 256 + tid;
        if (i < NQKV * DIMM) {
            int c = i >> 8, d = i & 255;
            int h = c / 96, t = c % 96, e = t / 3, s = t - e * 3;
            float v = Wq[i];
            int row = h * 32 + e;
            if (s == 0) {
                g_wq[row * DIMM + d] = v;
            } else {
                __nv_bfloat16 hh = __float2bfloat16(v);
                int brow = (s == 2) ? row : 256 + row;   // V rows 0-255, K rows 256-511
                g_wvkh[brow * DIMM + d] = hh;
                g_wvkl[brow * DIMM + d] = __float2bfloat16(v - __bfloat162float(hh));
                if (s == 1) g_wkt[d * 256 + row] = v;    // transposed for kmg
            }
        } else {
            int j = i - NQKV * DIMM;
            float v = Wp[j];
            __nv_bfloat16 hh = __float2bfloat16(v);
            g_wph[j] = hh;
            g_wpl[j] = __float2bfloat16(v - __bfloat162float(hh));
        }
        return;
    }
    int ball = blockIdx.x - 1024;
    if (tid < 3) {
        float s = 0.f;
        for (int m = 0; m < MB; m++) s += pos[(ball * MB + m) * 3 + tid];
        float mean = s * (1.f / MB);
        for (int m = 0; m < MB; m++)
            rel[m][tid] = pos[(ball * MB + m) * 3 + tid] - mean;
    }
    __syncthreads();
    int d = tid;
    float w0 = Wpe[d * 3 + 0], w1 = Wpe[d * 3 + 1], w2 = Wpe[d * 3 + 2];
    float b  = bpe[d];
    float xs = 0.f;
    #pragma unroll
    for (int m = 0; m < MB; m++) {
        int t = ball * MB + m;
        float v = x[t * DIMM + d]
                + rel[m][0] * w0 + rel[m][1] * w1 + rel[m][2] * w2 + b;
        g_xp[t * DIMM + d] = v;
        xs += v;
        __nv_bfloat16 h = __float2bfloat16(v);
        g_xph[t * DIMM + d] = h;
        g_xpl[t * DIMM + d] = __float2bfloat16(v - __bfloat162float(h));
    }
    g_xpm[ball * DIMM + d] = xs * (1.f / MB);
}

// ---------------- fp32 f32x2 GEMM-NT for Q (N=256), 128x128 tile, pipelined --------
__global__ void __launch_bounds__(256, 2)
k2_q(const float* __restrict__ bias) {
    __shared__ float As[2][16 * 132];
    __shared__ float Bs[2][16 * 132];
    int tid = threadIdx.x;
    int tx = tid & 15, ty = tid >> 4;
    int row0 = blockIdx.x * 128, col0 = blockIdx.y * 128;
    int r  = tid & 127;
    int k8 = (tid >> 7) * 8;

    const float* Ap = g_xp + (row0 + r) * DIMM + k8;
    const float* Bp = g_wq + (col0 + r) * DIMM + k8;

    float4 pa0 = *(const float4*)(Ap);
    float4 pa1 = *(const float4*)(Ap + 4);
    float4 pb0 = *(const float4*)(Bp);
    float4 pb1 = *(const float4*)(Bp + 4);

    ull accp[8][4] = {};
    #pragma unroll 2
    for (int c = 0; c < 16; c++) {
        float* A = As[c & 1];
        float* B = Bs[c & 1];
        A[(k8 + 0) * 132 + r] = pa0.x; A[(k8 + 1) * 132 + r] = pa0.y;
        A[(k8 + 2) * 132 + r] = pa0.z; A[(k8 + 3) * 132 + r] = pa0.w;
        A[(k8 + 4) * 132 + r] = pa1.x; A[(k8 + 5) * 132 + r] = pa1.y;
        A[(k8 + 6) * 132 + r] = pa1.z; A[(k8 + 7) * 132 + r] = pa1.w;
        B[(k8 + 0) * 132 + r] = pb0.x; B[(k8 + 1) * 132 + r] = pb0.y;
        B[(k8 + 2) * 132 + r] = pb0.z; B[(k8 + 3) * 132 + r] = pb0.w;
        B[(k8 + 4) * 132 + r] = pb1.x; B[(k8 + 5) * 132 + r] = pb1.y;
        B[(k8 + 6) * 132 + r] = pb1.z; B[(k8 + 7) * 132 + r] = pb1.w;
        __syncthreads();
        if (c < 15) {
            int k0n = (c + 1) * 16;
            pa0 = *(const float4*)(Ap + k0n);
            pa1 = *(const float4*)(Ap + k0n + 4);
            pb0 = *(const float4*)(Bp + k0n);
            pb1 = *(const float4*)(Bp + k0n + 4);
        }
        #pragma unroll
        for (int kk = 0; kk < 16; kk++) {
            float4 a0 = *(const float4*)(A + kk * 132 + ty * 4);
            float4 a1 = *(const float4*)(A + kk * 132 + 64 + ty * 4);
            float4 b0 = *(const float4*)(B + kk * 132 + tx * 4);
            float4 b1 = *(const float4*)(B + kk * 132 + 64 + tx * 4);
            ull bp[4] = {pack2(b0.x, b0.y), pack2(b0.z, b0.w),
                         pack2(b1.x, b1.y), pack2(b1.z, b1.w)};
            float av[8] = {a0.x, a0.y, a0.z, a0.w, a1.x, a1.y, a1.z, a1.w};
            #pragma unroll
            for (int i = 0; i < 8; i++) {
                ull ap = pack2(av[i], av[i]);
                #pragma unroll
                for (int j = 0; j < 4; j++) accp[i][j] = fma2(ap, bp[j], accp[i][j]);
            }
        }
    }
    float acc[8][8];
    #pragma unroll
    for (int i = 0; i < 8; i++)
        #pragma unroll
        for (int j = 0; j < 4; j++)
            unpack2(accp[i][j], acc[i][2 * j], acc[i][2 * j + 1]);
    #pragma unroll
    for (int i = 0; i < 8; i++) {
        int rr = row0 + ((i < 4) ? ty * 4 + i : 64 + ty * 4 + i - 4);
        #pragma unroll
        for (int j = 0; j < 8; j++) {
            int cp = col0 + ((j < 4) ? tx * 4 + j : 64 + tx * 4 + j - 4);
            int h = cp >> 5, e = cp & 31;
            float v = acc[i][j] + bias[h * 96 + e * 3];
            int qi = (h * NM + rr) * EE + e;
            g_q[qi] = v;
            __nv_bfloat16 b1 = __float2bfloat16(v);
            float f1 = __bfloat162float(b1);
            __nv_bfloat16 b2 = __float2bfloat16(v - f1);
            float f2 = __bfloat162float(b2);
            __nv_bfloat16 b3 = __float2bfloat16(v - f1 - f2);
            g_q1[qi] = b1; g_q2[qi] = b2; g_q3[qi] = b3;
        }
    }
}

// ---------------- split-bf16 HMMA GEMM-NT, 128x128 tile, cp.async pipelined --------
// MODE 0: A=g_xph/l, B=g_wvkh/l (N=512: V cols 0-255, K cols 256-511).
// MODE 1: A=g_aoh/l, B=g_wph/l (N=256) -> out.
template<int MODE>
__device__ __forceinline__ void issue_chunk(uint32_t stage, int row0, int col0,
                                            int k0, int tid) {
    const __nv_bfloat16* srcs[4] = {
        (MODE == 0) ? g_xph : g_aoh, (MODE == 0) ? g_xpl : g_aol,
        (MODE == 0) ? g_wvkh : g_wph, (MODE == 0) ? g_wvkl : g_wpl};
    #pragma unroll
    for (int b = 0; b < 4; b++) {
        int rbase = (b < 2) ? row0 : col0;
        #pragma unroll
        for (int l = 0; l < 4; l++) {
            int u = tid + l * 256;
            int r = u >> 3, cc = u & 7;
            const void* g = srcs[b] + (rbase + r) * DIMM + k0 + cc * 8;
            uint32_t off = (uint32_t)(r * 128 + cc * 16);
            off ^= (off >> 3) & 0x70;
            cpasync16(stage + b * 16384 + off, g);
        }
    }
    asm volatile("cp.async.commit_group;" ::: "memory");
}

template<int MODE>
__global__ void __launch_bounds__(256, 1)
gemm_mma(const float* __restrict__ bias, float* __restrict__ out) {
    extern __shared__ char dsm_raw[];
    int tid = threadIdx.x;
    int wid = tid >> 5, lane = tid & 31;
    int row0 = blockIdx.x * 128, col0 = blockIdx.y * 128;
    int warp_m = (wid & 1) * 64;
    int warp_n = (wid >> 1) * 32;

    uint32_t raw = smem_u32(dsm_raw);
    uint32_t sbase = (raw + 1023u) & ~1023u;

    float acc[4][4][4] = {};
    int lr = lane & 7;
    int g  = lane >> 3;

    issue_chunk<MODE>(sbase, row0, col0, 0, tid);

    for (int chunk = 0; chunk < 4; chunk++) {
        if (chunk < 3)
            issue_chunk<MODE>(sbase + ((chunk + 1) & 1) * 65536,
                              row0, col0, (chunk + 1) * 64, tid);
        if (chunk < 3)
            asm volatile("cp.async.wait_group 1;" ::: "memory");
        else
            asm volatile("cp.async.wait_group 0;" ::: "memory");
        __syncthreads();

        uint32_t st = sbase + (chunk & 1) * 65536;
        uint32_t aBuf[2] = {st, st + 16384};
        uint32_t bBuf[2] = {st + 32768, st + 49152};

        #pragma unroll
        for (int pass = 0; pass < 3; pass++) {
            uint32_t abase = aBuf[(pass == 2) ? 1 : 0];
            uint32_t bbase = bBuf[(pass == 1) ? 1 : 0];
            #pragma unroll
            for (int ks = 0; ks < 4; ks++) {
                uint32_t af[4][4];
                #pragma unroll
                for (int mi = 0; mi < 4; mi++) {
                    int row = warp_m + mi * 16 + ((g & 1) << 3) + lr;
                    int cb  = ks * 32 + ((g >> 1) << 4);
                    ldsm4(af[mi][0], af[mi][1], af[mi][2], af[mi][3],
                          swz_addr(abase, row, cb));
                }
                uint32_t bf[4][2];
                #pragma unroll
                for (int p = 0; p < 2; p++) {
                    int n  = warp_n + p * 16 + ((g >> 1) << 3) + lr;
                    int cb = ks * 32 + ((g & 1) << 4);
                    uint32_t r0, r1, r2, r3;
                    ldsm4(r0, r1, r2, r3, swz_addr(bbase, n, cb));
                    bf[p * 2 + 0][0] = r0; bf[p * 2 + 0][1] = r1;
                    bf[p * 2 + 1][0] = r2; bf[p * 2 + 1][1] = r3;
                }
                #pragma unroll
                for (int mi = 0; mi < 4; mi++)
                    #pragma unroll
                    for (int nj = 0; nj < 4; nj++)
                        mma16816(acc[mi][nj], af[mi], bf[nj][0], bf[nj][1]);
            }
        }
        __syncthreads();
    }

    int erow = lane >> 2;
    int ecol = (lane & 3) * 2;
    #pragma unroll
    for (int mi = 0; mi < 4; mi++) {
        #pragma unroll
        for (int nj = 0; nj < 4; nj++) {
            #pragma unroll
            for (int half = 0; half < 2; half++) {
                int r = row0 + warp_m + mi * 16 + erow + half * 8;
                #pragma unroll
                for (int rg = 0; rg < 2; rg++) {
                    int cp = col0 + warp_n + nj * 8 + ecol + rg;
                    float a = acc[mi][nj][half * 2 + rg];
                    if (MODE == 0) {
                        if (cp < 256) {   // V
                            int h = cp >> 5, e = cp & 31;
                            float v = a + bias[h * 96 + e * 3 + 2];
                            g_vh[(h * NM + r) * EE + e] = __float2half(v);
                        } else {          // K
                            int m = cp - 256;
                            int h = m >> 5, e = m & 31;
                            float v = a + bias[h * 96 + e * 3 + 1];
                            g_kh[(h * NM + r) * EE + e] = __float2half(v);
                        }
                    } else {
                        out[r * DIMM + cp] = a + bias[cp];
                    }
                }
            }
        }
    }
}

// ---------------- kmg: kmean = xpm @ Wk^T + bk (coalesced), fused 3-way split -------
// block = 8 balls; thread = output col; weights read transposed -> coalesced.
__global__ void __launch_bounds__(256)
kmg(const float* __restrict__ bias) {
    __shared__ float xm[8 * DIMM];
    int b0 = blockIdx.x * 8;
    int tid = threadIdx.x;
    #pragma unroll
    for (int i = 0; i < 8; i++)
        xm[i * DIMM + tid] = g_xpm[(b0 + i) * DIMM + tid];
    __syncthreads();

    float acc[8] = {};
    #pragma unroll 4
    for (int d = 0; d < DIMM; d++) {
        float w = g_wkt[d * 256 + tid];     // lane-contiguous: coalesced
        #pragma unroll
        for (int i = 0; i < 8; i++) acc[i] += xm[i * DIMM + d] * w;
    }
    int h = tid >> 5, e = tid & 31;
    float bk = bias[h * 96 + e * 3 + 1];
    #pragma unroll
    for (int i = 0; i < 8; i++) {
        float v = acc[i] + bk;
        int t = (h * NB + b0 + i) * EE + e;
        __nv_bfloat16 b1 = __float2bfloat16(v);
        float f1 = __bfloat162float(b1);
        __nv_bfloat16 b2 = __float2bfloat16(v - f1);
        float f2 = __bfloat162float(b2);
        __nv_bfloat16 b3 = __float2bfloat16(v - f1 - f2);
        g_km1[t] = b1; g_km2[t] = b2; g_km3[t] = b3;
    }
}

// ---------------- k4: sim via HMMA, 32 tok/warp, 4 chains, B prefetch ---------------
__device__ __forceinline__ void k4_load_b(uint32_t bfr[3][2][2], int h, int ball0,
                                          int mrow, int ep) {
    const __nv_bfloat16* ms[3] = {g_km1, g_km2, g_km3};
    #pragma unroll
    for (int s = 0; s < 3; s++) {
        const __nv_bfloat16* m = ms[s] + (h * NB + ball0 + mrow) * EE;
        #pragma unroll
        for (int kk = 0; kk < 2; kk++) {
            int e = kk * 16 + ep;
            bfr[s][kk][0] = *(const uint32_t*)(m + e);
            bfr[s][kk][1] = *(const uint32_t*)(m + e + 8);
        }
    }
}

__device__ __forceinline__ void top2_merge(float& v1, float& v2, int& i1, int& i2,
                                           float s, int c) {
    if (s > v1) { v2 = v1; i2 = i1; v1 = s; i1 = c; }
    else if (s > v2) { v2 = s; i2 = c; }
}

__global__ void __launch_bounds__(256, 2)
k4_top2() {
    int h = blockIdx.y;
    int tid = threadIdx.x;
    int wid = tid >> 5, lane = tid & 31;
    int tokw = blockIdx.x * 256 + wid * 32;
    int mrow = lane >> 2;
    int ep   = (lane & 3) * 2;

    const __nv_bfloat16* qs[3] = {g_q1, g_q2, g_q3};

    uint32_t afr[2][3][2][4];
    #pragma unroll
    for (int m = 0; m < 2; m++) {
        #pragma unroll
        for (int s = 0; s < 3; s++) {
            const __nv_bfloat16* q = qs[s] + (h * NM + tokw + m * 16) * EE;
            #pragma unroll
            for (int kk = 0; kk < 2; kk++) {
                int e = kk * 16 + ep;
                afr[m][s][kk][0] = *(const uint32_t*)(q + (mrow    ) * EE + e);
                afr[m][s][kk][1] = *(const uint32_t*)(q + (mrow + 8) * EE + e);
                afr[m][s][kk][2] = *(const uint32_t*)(q + (mrow    ) * EE + e + 8);
                afr[m][s][kk][3] = *(const uint32_t*)(q + (mrow + 8) * EE + e + 8);
            }
        }
    }

    float v1[4], v2[4];
    int   i1[4], i2[4];
    #pragma unroll
    for (int r = 0; r < 4; r++) { v1[r] = -1e30f; v2[r] = -1e30f; i1[r] = 0; i2[r] = 0; }

    uint32_t bf[2][3][2][2];
    k4_load_b(bf[0], h, 0, mrow, ep);

    #pragma unroll 2
    for (int grp = 0; grp < 64; grp++) {
        int cur = grp & 1;
        int ball0 = grp * 8;
        if (grp < 63)
            k4_load_b(bf[cur ^ 1], h, ball0 + 8, mrow, ep);

        float ac[4][4] = {};
        #pragma unroll
        for (int kk = 0; kk < 2; kk++) {
            uint32_t b00 = bf[cur][0][kk][0], b01 = bf[cur][0][kk][1];
            uint32_t b10 = bf[cur][1][kk][0], b11 = bf[cur][1][kk][1];
            uint32_t b20 = bf[cur][2][kk][0], b21 = bf[cur][2][kk][1];
            mma16816(ac[0], afr[0][0][kk], b00, b01);
            mma16816(ac[2], afr[1][0][kk], b00, b01);
            mma16816(ac[1], afr[0][0][kk], b10, b11);
            mma16816(ac[3], afr[1][0][kk], b10, b11);
            mma16816(ac[0], afr[0][1][kk], b00, b01);
            mma16816(ac[2], afr[1][1][kk], b00, b01);
            mma16816(ac[1], afr[0][1][kk], b10, b11);
            mma16816(ac[3], afr[1][1][kk], b10, b11);
            mma16816(ac[0], afr[0][0][kk], b20, b21);
            mma16816(ac[2], afr[1][0][kk], b20, b21);
            mma16816(ac[1], afr[0][2][kk], b00, b01);
            mma16816(ac[3], afr[1][2][kk], b00, b01);
        }

        int c0 = ball0 + ep, c1 = c0 + 1;
        #pragma unroll
        for (int m = 0; m < 2; m++) {
            float s0 = ac[2 * m][0] + ac[2 * m + 1][0];
            float s1 = ac[2 * m][1] + ac[2 * m + 1][1];
            float s2 = ac[2 * m][2] + ac[2 * m + 1][2];
            float s3 = ac[2 * m][3] + ac[2 * m + 1][3];
            int ra = m * 2, rb = m * 2 + 1;
            top2_merge(v1[ra], v2[ra], i1[ra], i2[ra], s0, c0);
            top2_merge(v1[ra], v2[ra], i1[ra], i2[ra], s1, c1);
            top2_merge(v1[rb], v2[rb], i1[rb], i2[rb], s2, c0);
            top2_merge(v1[rb], v2[rb], i1[rb], i2[rb], s3, c1);
        }
    }

    #pragma unroll
    for (int r = 0; r < 4; r++) {
        float a1 = v1[r], a2 = v2[r];
        int   b1 = i1[r], b2 = i2[r];
        #pragma unroll
        for (int d = 1; d < 4; d <<= 1) {
            float o1 = __shfl_xor_sync(0xffffffffu, a1, d);
            float o2 = __shfl_xor_sync(0xffffffffu, a2, d);
            int  oi1 = __shfl_xor_sync(0xffffffffu, b1, d);
            int  oi2 = __shfl_xor_sync(0xffffffffu, b2, d);
            if (o1 > a1) {
                if (a1 > o2) { a2 = a1; b2 = b1; } else { a2 = o2; b2 = oi2; }
                a1 = o1; b1 = oi1;
            } else if (o1 > a2) { a2 = o1; b2 = oi1; }
        }
        if ((lane & 3) == 0) {
            int tok = h * NM + tokw + (r >> 1) * 16 + (r & 1) * 8 + mrow;
            g_idx[tok * 2 + 0] = b1;
            g_idx[tok * 2 + 1] = b2;
        }
    }
}

// ---------------- k5: gathered 32-key attention (fp16 K,V) + bf16 split out ---------
__global__ void k5_attn() {
    int warp = (blockIdx.x * blockDim.x + threadIdx.x) >> 5;
    int lane = threadIdx.x & 31;
    int h = warp >> 13;
    int tok = warp & (NM - 1);
    int b0 = g_idx[warp * 2 + 0];
    int b1 = g_idx[warp * 2 + 1];

    int ball = (lane < 16) ? b0 : b1;
    int ktok = ball * MB + (lane & 15);
    const uint4*  kr4  = (const uint4*)(g_kh + (h * NM + ktok) * EE);
    const float4* qrow = (const float4*)(g_q + (h * NM + tok) * EE);
    float logit = 0.f;
    #pragma unroll
    for (int i = 0; i < 4; i++) {
        uint4 u = kr4[i];
        float4 qa = qrow[2 * i], qb = qrow[2 * i + 1];
        float2 k0 = __half22float2(*(__half2*)&u.x);
        float2 k1 = __half22float2(*(__half2*)&u.y);
        float2 k2 = __half22float2(*(__half2*)&u.z);
        float2 k3 = __half22float2(*(__half2*)&u.w);
        logit += qa.x * k0.x + qa.y * k0.y + qa.z * k1.x + qa.w * k1.y
               + qb.x * k2.x + qb.y * k2.y + qb.z * k3.x + qb.w * k3.y;
    }
    logit *= 0.17677669529663688f;

    float m = logit;
    #pragma unroll
    for (int off = 16; off > 0; off >>= 1)
        m = fmaxf(m, __shfl_xor_sync(0xffffffffu, m, off));
    float p = __expf(logit - m);
    float s = p;
    #pragma unroll
    for (int off = 16; off > 0; off >>= 1)
        s += __shfl_xor_sync(0xffffffffu, s, off);
    float attn = p / s;

    float out = 0.f;
    #pragma unroll
    for (int kk = 0; kk < NKEY; kk++) {
        float a = __shfl_sync(0xffffffffu, attn, kk);
        int kt = ((kk < 16) ? b0 : b1) * MB + (kk & 15);
        out += a * __half2float(g_vh[(h * NM + kt) * EE + lane]);
    }
    int oi = tok * DIMM + h * EE + lane;
    __nv_bfloat16 hi = __float2bfloat16(out);
    g_aoh[oi] = hi;
    g_aol[oi] = __float2bfloat16(out - __bfloat162float(hi));
}

// ---------------- launch --------------------------------------------------------------
extern "C" void kernel_launch(void* const* d_in, const int* in_sizes, int n_in,
                              void* d_out, int out_size) {
    const float* x     = (const float*)d_in[0];
    const float* pos   = (const float*)d_in[1];
    const float* Wqkv  = (const float*)d_in[2];
    const float* bqkv  = (const float*)d_in[3];
    const float* Wpe   = (const float*)d_in[4];
    const float* bpe   = (const float*)d_in[5];
    const float* Wproj = (const float*)d_in[6];
    const float* bproj = (const float*)d_in[7];
    float* out = (float*)d_out;

    const int DSMEM = 2 * 65536 + 1024;
    cudaFuncSetAttribute(gemm_mma<0>, cudaFuncAttributeMaxDynamicSharedMemorySize, DSMEM);
    cudaFuncSetAttribute(gemm_mma<1>, cudaFuncAttributeMaxDynamicSharedMemorySize, DSMEM);

    k01<<<1024 + NB, 256>>>(x, pos, Wpe, bpe, Wqkv, Wproj);
    k2_q<<<dim3(NM / 128, 2), 256>>>(bqkv);
    gemm_mma<0><<<dim3(NM / 128, 4), 256, DSMEM>>>(bqkv, nullptr);
    kmg<<<NB / 8, 256>>>(bqkv);
    k4_top2<<<dim3(NM / 256, NH), 256>>>();
    k5_attn<<<(NH * NM * 32) / 256, 256>>>();
    gemm_mma<1><<<dim3(NM / 128, DIMM / 128), 256, DSMEM>>>(bproj, out);
}

// round 16
// speedup vs baseline: 1.0513x; 1.0411x over previous
#include <cuda_runtime.h>
#include <cuda_bf16.h>
#include <cuda_fp16.h>
#include <cstdint>

#define NM   8192
#define DIMM 256
#define NH   8
#define EE   32
#define MB   16
#define NB   512
#define NKEY 32
#define NQKV 768

// ---------------- scratch ----------------------------------------------------
__device__ float g_xp[NM * DIMM];
__device__ __align__(16) __nv_bfloat16 g_xph[NM * DIMM];
__device__ __align__(16) __nv_bfloat16 g_xpl[NM * DIMM];
__device__ float g_wq[256 * DIMM];                  // permuted fp32 Q weights
__device__ float g_wkt[DIMM * 256];                 // transposed fp32 K weights [d][col]
__device__ __align__(16) __nv_bfloat16 g_wvkh[512 * DIMM];  // rows 0-255 V, 256-511 K
__device__ __align__(16) __nv_bfloat16 g_wvkl[512 * DIMM];
__device__ __align__(16) __nv_bfloat16 g_wph[DIMM * DIMM];
__device__ __align__(16) __nv_bfloat16 g_wpl[DIMM * DIMM];
__device__ __align__(16) __nv_bfloat16 g_aoh[NM * DIMM];
__device__ __align__(16) __nv_bfloat16 g_aol[NM * DIMM];
__device__ float g_q[NH * NM * EE];
__device__ __align__(16) __half g_kh[NH * NM * EE];  // fp16 K (k5 logits)
__device__ __align__(16) __half g_vh[NH * NM * EE];  // fp16 V
__device__ float g_xpm[NB * DIMM];                   // per-ball mean of xp
__device__ int   g_idx[NH * NM * 2];
// 3-way bf16 splits for the selection GEMM (exact to ~2^-25)
__device__ __align__(16) __nv_bfloat16 g_q1[NH * NM * EE];
__device__ __align__(16) __nv_bfloat16 g_q2[NH * NM * EE];
__device__ __align__(16) __nv_bfloat16 g_q3[NH * NM * EE];
__device__ __align__(16) __nv_bfloat16 g_km1[NH * NB * EE];
__device__ __align__(16) __nv_bfloat16 g_km2[NH * NB * EE];
__device__ __align__(16) __nv_bfloat16 g_km3[NH * NB * EE];

// ---------------- packed f32x2 helpers ----------------------------------------
typedef unsigned long long ull;
__device__ __forceinline__ ull pack2(float x, float y) {
    ull r; asm("mov.b64 %0, {%1, %2};" : "=l"(r) : "f"(x), "f"(y)); return r;
}
__device__ __forceinline__ ull fma2(ull a, ull b, ull c) {
    ull d; asm("fma.rn.f32x2 %0, %1, %2, %3;" : "=l"(d) : "l"(a), "l"(b), "l"(c));
    return d;
}
__device__ __forceinline__ void unpack2(ull v, float& lo, float& hi) {
    asm("mov.b64 {%0, %1}, %2;" : "=f"(lo), "=f"(hi) : "l"(v));
}

// ---------------- mma.sync helpers ---------------------------------------------
__device__ __forceinline__ uint32_t smem_u32(const void* p) {
    uint32_t a;
    asm("{ .reg .u64 t; cvta.to.shared.u64 t, %1; cvt.u32.u64 %0, t; }" : "=r"(a) : "l"(p));
    return a;
}
__device__ __forceinline__ uint32_t swz_addr(uint32_t base, int r, int cb) {
    uint32_t off = (uint32_t)(r * 128 + cb);
    off ^= (off >> 3) & 0x70;
    return base + off;
}
__device__ __forceinline__ void ldsm4(uint32_t& r0, uint32_t& r1, uint32_t& r2,
                                      uint32_t& r3, uint32_t addr) {
    asm volatile("ldmatrix.sync.aligned.m8n8.x4.shared.b16 {%0,%1,%2,%3}, [%4];"
                 : "=r"(r0), "=r"(r1), "=r"(r2), "=r"(r3) : "r"(addr));
}
__device__ __forceinline__ void mma16816(float* d, const uint32_t* a,
                                         uint32_t b0, uint32_t b1) {
    asm volatile(
        "mma.sync.aligned.m16n8k16.row.col.f32.bf16.bf16.f32 "
        "{%0,%1,%2,%3}, {%4,%5,%6,%7}, {%8,%9}, {%0,%1,%2,%3};"
        : "+f"(d[0]), "+f"(d[1]), "+f"(d[2]), "+f"(d[3])
        : "r"(a[0]), "r"(a[1]), "r"(a[2]), "r"(a[3]), "r"(b0), "r"(b1));
}
__device__ __forceinline__ void cpasync16(uint32_t dst, const void* src) {
    asm volatile("cp.async.cg.shared.global [%0], [%1], 16;" :: "r"(dst), "l"(src));
}

// ---------------- k01: weight permutation/splits + PE add + xp ball means ----------
__global__ void k01(const float* __restrict__ x, const float* __restrict__ pos,
                    const float* __restrict__ Wpe, const float* __restrict__ bpe,
                    const float* __restrict__ Wq, const float* __restrict__ Wp) {
    __shared__ float rel[MB][3];
    int tid = threadIdx.x;
    if (blockIdx.x < 1024) {
        int i = blockIdx.x * 256 + tid;
        if (i < NQKV * DIMM) {
            int c = i >> 8, d = i & 255;
            int h = c / 96, t = c % 96, e = t / 3, s = t - e * 3;
            float v = Wq[i];
            int row = h * 32 + e;
            if (s == 0) {
                g_wq[row * DIMM + d] = v;
            } else {
                __nv_bfloat16 hh = __float2bfloat16(v);
                int brow = (s == 2) ? row : 256 + row;   // V rows 0-255, K rows 256-511
                g_wvkh[brow * DIMM + d] = hh;
                g_wvkl[brow * DIMM + d] = __float2bfloat16(v - __bfloat162float(hh));
                if (s == 1) g_wkt[d * 256 + row] = v;    // transposed for kmg
            }
        } else {
            int j = i - NQKV * DIMM;
            float v = Wp[j];
            __nv_bfloat16 hh = __float2bfloat16(v);
            g_wph[j] = hh;
            g_wpl[j] = __float2bfloat16(v - __bfloat162float(hh));
        }
        return;
    }
    int ball = blockIdx.x - 1024;
    if (tid < 3) {
        float s = 0.f;
        for (int m = 0; m < MB; m++) s += pos[(ball * MB + m) * 3 + tid];
        float mean = s * (1.f / MB);
        for (int m = 0; m < MB; m++)
            rel[m][tid] = pos[(ball * MB + m) * 3 + tid] - mean;
    }
    __syncthreads();
    int d = tid;
    float w0 = Wpe[d * 3 + 0], w1 = Wpe[d * 3 + 1], w2 = Wpe[d * 3 + 2];
    float b  = bpe[d];
    float xs = 0.f;
    #pragma unroll
    for (int m = 0; m < MB; m++) {
        int t = ball * MB + m;
        float v = x[t * DIMM + d]
                + rel[m][0] * w0 + rel[m][1] * w1 + rel[m][2] * w2 + b;
        g_xp[t * DIMM + d] = v;
        xs += v;
        __nv_bfloat16 h = __float2bfloat16(v);
        g_xph[t * DIMM + d] = h;
        g_xpl[t * DIMM + d] = __float2bfloat16(v - __bfloat162float(h));
    }
    g_xpm[ball * DIMM + d] = xs * (1.f / MB);
}

// ---------------- fp32 f32x2 GEMM-NT for Q (N=256), 128x128 tile, pipelined --------
__global__ void __launch_bounds__(256, 2)
k2_q(const float* __restrict__ bias) {
    __shared__ float As[2][16 * 132];
    __shared__ float Bs[2][16 * 132];
    int tid = threadIdx.x;
    int tx = tid & 15, ty = tid >> 4;
    int row0 = blockIdx.x * 128, col0 = blockIdx.y * 128;
    int r  = tid & 127;
    int k8 = (tid >> 7) * 8;

    const float* Ap = g_xp + (row0 + r) * DIMM + k8;
    const float* Bp = g_wq + (col0 + r) * DIMM + k8;

    float4 pa0 = *(const float4*)(Ap);
    float4 pa1 = *(const float4*)(Ap + 4);
    float4 pb0 = *(const float4*)(Bp);
    float4 pb1 = *(const float4*)(Bp + 4);

    ull accp[8][4] = {};
    #pragma unroll 2
    for (int c = 0; c < 16; c++) {
        float* A = As[c & 1];
        float* B = Bs[c & 1];
        A[(k8 + 0) * 132 + r] = pa0.x; A[(k8 + 1) * 132 + r] = pa0.y;
        A[(k8 + 2) * 132 + r] = pa0.z; A[(k8 + 3) * 132 + r] = pa0.w;
        A[(k8 + 4) * 132 + r] = pa1.x; A[(k8 + 5) * 132 + r] = pa1.y;
        A[(k8 + 6) * 132 + r] = pa1.z; A[(k8 + 7) * 132 + r] = pa1.w;
        B[(k8 + 0) * 132 + r] = pb0.x; B[(k8 + 1) * 132 + r] = pb0.y;
        B[(k8 + 2) * 132 + r] = pb0.z; B[(k8 + 3) * 132 + r] = pb0.w;
        B[(k8 + 4) * 132 + r] = pb1.x; B[(k8 + 5) * 132 + r] = pb1.y;
        B[(k8 + 6) * 132 + r] = pb1.z; B[(k8 + 7) * 132 + r] = pb1.w;
        __syncthreads();
        if (c < 15) {
            int k0n = (c + 1) * 16;
            pa0 = *(const float4*)(Ap + k0n);
            pa1 = *(const float4*)(Ap + k0n + 4);
            pb0 = *(const float4*)(Bp + k0n);
            pb1 = *(const float4*)(Bp + k0n + 4);
        }
        #pragma unroll
        for (int kk = 0; kk < 16; kk++) {
            float4 a0 = *(const float4*)(A + kk * 132 + ty * 4);
            float4 a1 = *(const float4*)(A + kk * 132 + 64 + ty * 4);
            float4 b0 = *(const float4*)(B + kk * 132 + tx * 4);
            float4 b1 = *(const float4*)(B + kk * 132 + 64 + tx * 4);
            ull bp[4] = {pack2(b0.x, b0.y), pack2(b0.z, b0.w),
                         pack2(b1.x, b1.y), pack2(b1.z, b1.w)};
            float av[8] = {a0.x, a0.y, a0.z, a0.w, a1.x, a1.y, a1.z, a1.w};
            #pragma unroll
            for (int i = 0; i < 8; i++) {
                ull ap = pack2(av[i], av[i]);
                #pragma unroll
                for (int j = 0; j < 4; j++) accp[i][j] = fma2(ap, bp[j], accp[i][j]);
            }
        }
    }
    float acc[8][8];
    #pragma unroll
    for (int i = 0; i < 8; i++)
        #pragma unroll
        for (int j = 0; j < 4; j++)
            unpack2(accp[i][j], acc[i][2 * j], acc[i][2 * j + 1]);
    #pragma unroll
    for (int i = 0; i < 8; i++) {
        int rr = row0 + ((i < 4) ? ty * 4 + i : 64 + ty * 4 + i - 4);
        #pragma unroll
        for (int j = 0; j < 8; j++) {
            int cp = col0 + ((j < 4) ? tx * 4 + j : 64 + tx * 4 + j - 4);
            int h = cp >> 5, e = cp & 31;
            float v = acc[i][j] + bias[h * 96 + e * 3];
            int qi = (h * NM + rr) * EE + e;
            g_q[qi] = v;
            __nv_bfloat16 b1 = __float2bfloat16(v);
            float f1 = __bfloat162float(b1);
            __nv_bfloat16 b2 = __float2bfloat16(v - f1);
            float f2 = __bfloat162float(b2);
            __nv_bfloat16 b3 = __float2bfloat16(v - f1 - f2);
            g_q1[qi] = b1; g_q2[qi] = b2; g_q3[qi] = b3;
        }
    }
}

// ---------------- split-bf16 HMMA GEMM-NT, 128x128 tile, cp.async pipelined --------
// MODE 0: A=g_xph/l, B=g_wvkh/l (N=512: V cols 0-255, K cols 256-511).
// MODE 1: A=g_aoh/l, B=g_wph/l (N=256) -> out.
template<int MODE>
__device__ __forceinline__ void issue_chunk(uint32_t stage, int row0, int col0,
                                            int k0, int tid) {
    const __nv_bfloat16* srcs[4] = {
        (MODE == 0) ? g_xph : g_aoh, (MODE == 0) ? g_xpl : g_aol,
        (MODE == 0) ? g_wvkh : g_wph, (MODE == 0) ? g_wvkl : g_wpl};
    #pragma unroll
    for (int b = 0; b < 4; b++) {
        int rbase = (b < 2) ? row0 : col0;
        #pragma unroll
        for (int l = 0; l < 4; l++) {
            int u = tid + l * 256;
            int r = u >> 3, cc = u & 7;
            const void* g = srcs[b] + (rbase + r) * DIMM + k0 + cc * 8;
            uint32_t off = (uint32_t)(r * 128 + cc * 16);
            off ^= (off >> 3) & 0x70;
            cpasync16(stage + b * 16384 + off, g);
        }
    }
    asm volatile("cp.async.commit_group;" ::: "memory");
}

template<int MODE>
__global__ void __launch_bounds__(256, 1)
gemm_mma(const float* __restrict__ bias, float* __restrict__ out) {
    extern __shared__ char dsm_raw[];
    int tid = threadIdx.x;
    int wid = tid >> 5, lane = tid & 31;
    int row0 = blockIdx.x * 128, col0 = blockIdx.y * 128;
    int warp_m = (wid & 1) * 64;
    int warp_n = (wid >> 1) * 32;

    uint32_t raw = smem_u32(dsm_raw);
    uint32_t sbase = (raw + 1023u) & ~1023u;

    float acc[4][4][4] = {};
    int lr = lane & 7;
    int g  = lane >> 3;

    issue_chunk<MODE>(sbase, row0, col0, 0, tid);

    for (int chunk = 0; chunk < 4; chunk++) {
        if (chunk < 3)
            issue_chunk<MODE>(sbase + ((chunk + 1) & 1) * 65536,
                              row0, col0, (chunk + 1) * 64, tid);
        if (chunk < 3)
            asm volatile("cp.async.wait_group 1;" ::: "memory");
        else
            asm volatile("cp.async.wait_group 0;" ::: "memory");
        __syncthreads();

        uint32_t st = sbase + (chunk & 1) * 65536;
        uint32_t aBuf[2] = {st, st + 16384};
        uint32_t bBuf[2] = {st + 32768, st + 49152};

        #pragma unroll
        for (int pass = 0; pass < 3; pass++) {
            uint32_t abase = aBuf[(pass == 2) ? 1 : 0];
            uint32_t bbase = bBuf[(pass == 1) ? 1 : 0];
            #pragma unroll
            for (int ks = 0; ks < 4; ks++) {
                uint32_t af[4][4];
                #pragma unroll
                for (int mi = 0; mi < 4; mi++) {
                    int row = warp_m + mi * 16 + ((g & 1) << 3) + lr;
                    int cb  = ks * 32 + ((g >> 1) << 4);
                    ldsm4(af[mi][0], af[mi][1], af[mi][2], af[mi][3],
                          swz_addr(abase, row, cb));
                }
                uint32_t bf[4][2];
                #pragma unroll
                for (int p = 0; p < 2; p++) {
                    int n  = warp_n + p * 16 + ((g >> 1) << 3) + lr;
                    int cb = ks * 32 + ((g & 1) << 4);
                    uint32_t r0, r1, r2, r3;
                    ldsm4(r0, r1, r2, r3, swz_addr(bbase, n, cb));
                    bf[p * 2 + 0][0] = r0; bf[p * 2 + 0][1] = r1;
                    bf[p * 2 + 1][0] = r2; bf[p * 2 + 1][1] = r3;
                }
                #pragma unroll
                for (int mi = 0; mi < 4; mi++)
                    #pragma unroll
                    for (int nj = 0; nj < 4; nj++)
                        mma16816(acc[mi][nj], af[mi], bf[nj][0], bf[nj][1]);
            }
        }
        __syncthreads();
    }

    int erow = lane >> 2;
    int ecol = (lane & 3) * 2;
    #pragma unroll
    for (int mi = 0; mi < 4; mi++) {
        #pragma unroll
        for (int nj = 0; nj < 4; nj++) {
            #pragma unroll
            for (int half = 0; half < 2; half++) {
                int r = row0 + warp_m + mi * 16 + erow + half * 8;
                #pragma unroll
                for (int rg = 0; rg < 2; rg++) {
                    int cp = col0 + warp_n + nj * 8 + ecol + rg;
                    float a = acc[mi][nj][half * 2 + rg];
                    if (MODE == 0) {
                        if (cp < 256) {   // V
                            int h = cp >> 5, e = cp & 31;
                            float v = a + bias[h * 96 + e * 3 + 2];
                            g_vh[(h * NM + r) * EE + e] = __float2half(v);
                        } else {          // K
                            int m = cp - 256;
                            int h = m >> 5, e = m & 31;
                            float v = a + bias[h * 96 + e * 3 + 1];
                            g_kh[(h * NM + r) * EE + e] = __float2half(v);
                        }
                    } else {
                        out[r * DIMM + cp] = a + bias[cp];
                    }
                }
            }
        }
    }
}

// ---------------- kmg: kmean = xpm @ Wk^T + bk -- 256 CTAs, d-sliced ----------------
// grid (64 ballgroups, 4 colgroups); thread = (col in 64, d-slice in 4).
__global__ void __launch_bounds__(256)
kmg(const float* __restrict__ bias) {
    __shared__ float xm[8 * DIMM];              // 8 balls x 256
    __shared__ float part[8 * 4 * 64];          // [i][ds][col64]
    int b0 = blockIdx.x * 8;
    int cg = blockIdx.y;
    int tid = threadIdx.x;
    #pragma unroll
    for (int i = 0; i < 8; i++)
        xm[i * DIMM + tid] = g_xpm[(b0 + i) * DIMM + tid];
    __syncthreads();

    int c64 = tid & 63;
    int ds  = tid >> 6;                         // 0..3
    int col = cg * 64 + c64;
    float acc[8] = {};
    #pragma unroll 4
    for (int dd = 0; dd < 64; dd++) {
        int d = ds * 64 + dd;
        float w = g_wkt[d * 256 + col];         // 64 consecutive cols: coalesced
        #pragma unroll
        for (int i = 0; i < 8; i++) acc[i] += xm[i * DIMM + d] * w;
    }
    #pragma unroll
    for (int i = 0; i < 8; i++)
        part[(i * 4 + ds) * 64 + c64] = acc[i];
    __syncthreads();

    // 512 outputs per block; threads handle 2 each: (i, col64)
    #pragma unroll
    for (int o = 0; o < 2; o++) {
        int oi = tid + o * 256;
        int i = oi >> 6;
        int cc = oi & 63;
        float v = (part[(i * 4 + 0) * 64 + cc] + part[(i * 4 + 1) * 64 + cc])
                + (part[(i * 4 + 2) * 64 + cc] + part[(i * 4 + 3) * 64 + cc]);
        int colo = cg * 64 + cc;
        int h = colo >> 5, e = colo & 31;
        v += bias[h * 96 + e * 3 + 1];
        int t = (h * NB + b0 + i) * EE + e;
        __nv_bfloat16 b1 = __float2bfloat16(v);
        float f1 = __bfloat162float(b1);
        __nv_bfloat16 b2 = __float2bfloat16(v - f1);
        float f2 = __bfloat162float(b2);
        __nv_bfloat16 b3 = __float2bfloat16(v - f1 - f2);
        g_km1[t] = b1; g_km2[t] = b2; g_km3[t] = b3;
    }
}

// ---------------- k4: sim via HMMA, 32 tok/warp, 4 chains, B prefetch ---------------
__device__ __forceinline__ void k4_load_b(uint32_t bfr[3][2][2], int h, int ball0,
                                          int mrow, int ep) {
    const __nv_bfloat16* ms[3] = {g_km1, g_km2, g_km3};
    #pragma unroll
    for (int s = 0; s < 3; s++) {
        const __nv_bfloat16* m = ms[s] + (h * NB + ball0 + mrow) * EE;
        #pragma unroll
        for (int kk = 0; kk < 2; kk++) {
            int e = kk * 16 + ep;
            bfr[s][kk][0] = *(const uint32_t*)(m + e);
            bfr[s][kk][1] = *(const uint32_t*)(m + e + 8);
        }
    }
}

__device__ __forceinline__ void top2_merge(float& v1, float& v2, int& i1, int& i2,
                                           float s, int c) {
    if (s > v1) { v2 = v1; i2 = i1; v1 = s; i1 = c; }
    else if (s > v2) { v2 = s; i2 = c; }
}

__global__ void __launch_bounds__(256, 2)
k4_top2() {
    int h = blockIdx.y;
    int tid = threadIdx.x;
    int wid = tid >> 5, lane = tid & 31;
    int tokw = blockIdx.x * 256 + wid * 32;
    int mrow = lane >> 2;
    int ep   = (lane & 3) * 2;

    const __nv_bfloat16* qs[3] = {g_q1, g_q2, g_q3};

    uint32_t afr[2][3][2][4];
    #pragma unroll
    for (int m = 0; m < 2; m++) {
        #pragma unroll
        for (int s = 0; s < 3; s++) {
            const __nv_bfloat16* q = qs[s] + (h * NM + tokw + m * 16) * EE;
            #pragma unroll
            for (int kk = 0; kk < 2; kk++) {
                int e = kk * 16 + ep;
                afr[m][s][kk][0] = *(const uint32_t*)(q + (mrow    ) * EE + e);
                afr[m][s][kk][1] = *(const uint32_t*)(q + (mrow + 8) * EE + e);
                afr[m][s][kk][2] = *(const uint32_t*)(q + (mrow    ) * EE + e + 8);
                afr[m][s][kk][3] = *(const uint32_t*)(q + (mrow + 8) * EE + e + 8);
            }
        }
    }

    float v1[4], v2[4];
    int   i1[4], i2[4];
    #pragma unroll
    for (int r = 0; r < 4; r++) { v1[r] = -1e30f; v2[r] = -1e30f; i1[r] = 0; i2[r] = 0; }

    uint32_t bf[2][3][2][2];
    k4_load_b(bf[0], h, 0, mrow, ep);

    #pragma unroll 2
    for (int grp = 0; grp < 64; grp++) {
        int cur = grp & 1;
        int ball0 = grp * 8;
        if (grp < 63)
            k4_load_b(bf[cur ^ 1], h, ball0 + 8, mrow, ep);

        float ac[4][4] = {};
        #pragma unroll
        for (int kk = 0; kk < 2; kk++) {
            uint32_t b00 = bf[cur][0][kk][0], b01 = bf[cur][0][kk][1];
            uint32_t b10 = bf[cur][1][kk][0], b11 = bf[cur][1][kk][1];
            uint32_t b20 = bf[cur][2][kk][0], b21 = bf[cur][2][kk][1];
            mma16816(ac[0], afr[0][0][kk], b00, b01);
            mma16816(ac[2], afr[1][0][kk], b00, b01);
            mma16816(ac[1], afr[0][0][kk], b10, b11);
            mma16816(ac[3], afr[1][0][kk], b10, b11);
            mma16816(ac[0], afr[0][1][kk], b00, b01);
            mma16816(ac[2], afr[1][1][kk], b00, b01);
            mma16816(ac[1], afr[0][1][kk], b10, b11);
            mma16816(ac[3], afr[1][1][kk], b10, b11);
            mma16816(ac[0], afr[0][0][kk], b20, b21);
            mma16816(ac[2], afr[1][0][kk], b20, b21);
            mma16816(ac[1], afr[0][2][kk], b00, b01);
            mma16816(ac[3], afr[1][2][kk], b00, b01);
        }

        int c0 = ball0 + ep, c1 = c0 + 1;
        #pragma unroll
        for (int m = 0; m < 2; m++) {
            float s0 = ac[2 * m][0] + ac[2 * m + 1][0];
            float s1 = ac[2 * m][1] + ac[2 * m + 1][1];
            float s2 = ac[2 * m][2] + ac[2 * m + 1][2];
            float s3 = ac[2 * m][3] + ac[2 * m + 1][3];
            int ra = m * 2, rb = m * 2 + 1;
            top2_merge(v1[ra], v2[ra], i1[ra], i2[ra], s0, c0);
            top2_merge(v1[ra], v2[ra], i1[ra], i2[ra], s1, c1);
            top2_merge(v1[rb], v2[rb], i1[rb], i2[rb], s2, c0);
            top2_merge(v1[rb], v2[rb], i1[rb], i2[rb], s3, c1);
        }
    }

    #pragma unroll
    for (int r = 0; r < 4; r++) {
        float a1 = v1[r], a2 = v2[r];
        int   b1 = i1[r], b2 = i2[r];
        #pragma unroll
        for (int d = 1; d < 4; d <<= 1) {
            float o1 = __shfl_xor_sync(0xffffffffu, a1, d);
            float o2 = __shfl_xor_sync(0xffffffffu, a2, d);
            int  oi1 = __shfl_xor_sync(0xffffffffu, b1, d);
            int  oi2 = __shfl_xor_sync(0xffffffffu, b2, d);
            if (o1 > a1) {
                if (a1 > o2) { a2 = a1; b2 = b1; } else { a2 = o2; b2 = oi2; }
                a1 = o1; b1 = oi1;
            } else if (o1 > a2) { a2 = o1; b2 = oi1; }
        }
        if ((lane & 3) == 0) {
            int tok = h * NM + tokw + (r >> 1) * 16 + (r & 1) * 8 + mrow;
            g_idx[tok * 2 + 0] = b1;
            g_idx[tok * 2 + 1] = b2;
        }
    }
}

// ---------------- k5: gathered 32-key attention (fp16 K,V) + bf16 split out ---------
__global__ void k5_attn() {
    int warp = (blockIdx.x * blockDim.x + threadIdx.x) >> 5;
    int lane = threadIdx.x & 31;
    int h = warp >> 13;
    int tok = warp & (NM - 1);
    int b0 = g_idx[warp * 2 + 0];
    int b1 = g_idx[warp * 2 + 1];

    int ball = (lane < 16) ? b0 : b1;
    int ktok = ball * MB + (lane & 15);
    const uint4*  kr4  = (const uint4*)(g_kh + (h * NM + ktok) * EE);
    const float4* qrow = (const float4*)(g_q + (h * NM + tok) * EE);
    float logit = 0.f;
    #pragma unroll
    for (int i = 0; i < 4; i++) {
        uint4 u = kr4[i];
        float4 qa = qrow[2 * i], qb = qrow[2 * i + 1];
        float2 k0 = __half22float2(*(__half2*)&u.x);
        float2 k1 = __half22float2(*(__half2*)&u.y);
        float2 k2 = __half22float2(*(__half2*)&u.z);
        float2 k3 = __half22float2(*(__half2*)&u.w);
        logit += qa.x * k0.x + qa.y * k0.y + qa.z * k1.x + qa.w * k1.y
               + qb.x * k2.x + qb.y * k2.y + qb.z * k3.x + qb.w * k3.y;
    }
    logit *= 0.17677669529663688f;

    float m = logit;
    #pragma unroll
    for (int off = 16; off > 0; off >>= 1)
        m = fmaxf(m, __shfl_xor_sync(0xffffffffu, m, off));
    float p = __expf(logit - m);
    float s = p;
    #pragma unroll
    for (int off = 16; off > 0; off >>= 1)
        s += __shfl_xor_sync(0xffffffffu, s, off);
    float attn = p / s;

    float out = 0.f;
    #pragma unroll
    for (int kk = 0; kk < NKEY; kk++) {
        float a = __shfl_sync(0xffffffffu, attn, kk);
        int kt = ((kk < 16) ? b0 : b1) * MB + (kk & 15);
        out += a * __half2float(g_vh[(h * NM + kt) * EE + lane]);
    }
    int oi = tok * DIMM + h * EE + lane;
    __nv_bfloat16 hi = __float2bfloat16(out);
    g_aoh[oi] = hi;
    g_aol[oi] = __float2bfloat16(out - __bfloat162float(hi));
}

// ---------------- launch --------------------------------------------------------------
extern "C" void kernel_launch(void* const* d_in, const int* in_sizes, int n_in,
                              void* d_out, int out_size) {
    const float* x     = (const float*)d_in[0];
    const float* pos   = (const float*)d_in[1];
    const float* Wqkv  = (const float*)d_in[2];
    const float* bqkv  = (const float*)d_in[3];
    const float* Wpe   = (const float*)d_in[4];
    const float* bpe   = (const float*)d_in[5];
    const float* Wproj = (const float*)d_in[6];
    const float* bproj = (const float*)d_in[7];
    float* out = (float*)d_out;

    const int DSMEM = 2 * 65536 + 1024;
    cudaFuncSetAttribute(gemm_mma<0>, cudaFuncAttributeMaxDynamicSharedMemorySize, DSMEM);
    cudaFuncSetAttribute(gemm_mma<1>, cudaFuncAttributeMaxDynamicSharedMemorySize, DSMEM);

    k01<<<1024 + NB, 256>>>(x, pos, Wpe, bpe, Wqkv, Wproj);
    k2_q<<<dim3(NM / 128, 2), 256>>>(bqkv);
    gemm_mma<0><<<dim3(NM / 128, 4), 256, DSMEM>>>(bqkv, nullptr);
    kmg<<<dim3(NB / 8, 4), 256>>>(bqkv);
    k4_top2<<<dim3(NM / 256, NH), 256>>>();
    k5_attn<<<(NH * NM * 32) / 256, 256>>>();
    gemm_mma<1><<<dim3(NM / 128, DIMM / 128), 256, DSMEM>>>(bproj, out);
}

// round 17
// speedup vs baseline: 1.0622x; 1.0104x over previous
#include <cuda_runtime.h>
#include <cuda_bf16.h>
#include <cuda_fp16.h>
#include <cstdint>

#define NM   8192
#define DIMM 256
#define NH   8
#define EE   32
#define MB   16
#define NB   512
#define NKEY 32
#define NQKV 768

// ---------------- scratch ----------------------------------------------------
__device__ float g_xp[NM * DIMM];
__device__ __align__(16) __nv_bfloat16 g_xph[NM * DIMM];
__device__ __align__(16) __nv_bfloat16 g_xpl[NM * DIMM];
__device__ float g_wq[256 * DIMM];                  // permuted fp32 Q weights
__device__ float g_wkt[DIMM * 256];                 // transposed fp32 K weights [d][col]
__device__ __align__(16) __nv_bfloat16 g_wvkh[512 * DIMM];  // rows 0-255 V, 256-511 K
__device__ __align__(16) __nv_bfloat16 g_wvkl[512 * DIMM];
__device__ __align__(16) __nv_bfloat16 g_wph[DIMM * DIMM];
__device__ __align__(16) __nv_bfloat16 g_wpl[DIMM * DIMM];
__device__ __align__(16) __nv_bfloat16 g_aoh[NM * DIMM];
__device__ __align__(16) __nv_bfloat16 g_aol[NM * DIMM];
__device__ float g_q[NH * NM * EE];
__device__ __align__(16) __half g_kh[NH * NM * EE];  // fp16 K (k5 logits)
__device__ __align__(16) __half g_vh[NH * NM * EE];  // fp16 V
__device__ float g_xpm[NB * DIMM];                   // per-ball mean of xp
__device__ int   g_idx[NH * NM * 2];
// 3-way bf16 splits for the selection GEMM (exact to ~2^-25)
__device__ __align__(16) __nv_bfloat16 g_q1[NH * NM * EE];
__device__ __align__(16) __nv_bfloat16 g_q2[NH * NM * EE];
__device__ __align__(16) __nv_bfloat16 g_q3[NH * NM * EE];
__device__ __align__(16) __nv_bfloat16 g_km1[NH * NB * EE];
__device__ __align__(16) __nv_bfloat16 g_km2[NH * NB * EE];
__device__ __align__(16) __nv_bfloat16 g_km3[NH * NB * EE];

// ---------------- packed f32x2 helpers ----------------------------------------
typedef unsigned long long ull;
__device__ __forceinline__ ull pack2(float x, float y) {
    ull r; asm("mov.b64 %0, {%1, %2};" : "=l"(r) : "f"(x), "f"(y)); return r;
}
__device__ __forceinline__ ull fma2(ull a, ull b, ull c) {
    ull d; asm("fma.rn.f32x2 %0, %1, %2, %3;" : "=l"(d) : "l"(a), "l"(b), "l"(c));
    return d;
}
__device__ __forceinline__ void unpack2(ull v, float& lo, float& hi) {
    asm("mov.b64 {%0, %1}, %2;" : "=f"(lo), "=f"(hi) : "l"(v));
}

// ---------------- mma.sync helpers ---------------------------------------------
__device__ __forceinline__ uint32_t smem_u32(const void* p) {
    uint32_t a;
    asm("{ .reg .u64 t; cvta.to.shared.u64 t, %1; cvt.u32.u64 %0, t; }" : "=r"(a) : "l"(p));
    return a;
}
__device__ __forceinline__ uint32_t swz_addr(uint32_t base, int r, int cb) {
    uint32_t off = (uint32_t)(r * 128 + cb);
    off ^= (off >> 3) & 0x70;
    return base + off;
}
__device__ __forceinline__ void ldsm4(uint32_t& r0, uint32_t& r1, uint32_t& r2,
                                      uint32_t& r3, uint32_t addr) {
    asm volatile("ldmatrix.sync.aligned.m8n8.x4.shared.b16 {%0,%1,%2,%3}, [%4];"
                 : "=r"(r0), "=r"(r1), "=r"(r2), "=r"(r3) : "r"(addr));
}
__device__ __forceinline__ void mma16816(float* d, const uint32_t* a,
                                         uint32_t b0, uint32_t b1) {
    asm volatile(
        "mma.sync.aligned.m16n8k16.row.col.f32.bf16.bf16.f32 "
        "{%0,%1,%2,%3}, {%4,%5,%6,%7}, {%8,%9}, {%0,%1,%2,%3};"
        : "+f"(d[0]), "+f"(d[1]), "+f"(d[2]), "+f"(d[3])
        : "r"(a[0]), "r"(a[1]), "r"(a[2]), "r"(a[3]), "r"(b0), "r"(b1));
}
__device__ __forceinline__ void cpasync16(uint32_t dst, const void* src) {
    asm volatile("cp.async.cg.shared.global [%0], [%1], 16;" :: "r"(dst), "l"(src));
}

// ---------------- k01: weight permutation/splits + PE add + xp ball means ----------
__global__ void k01(const float* __restrict__ x, const float* __restrict__ pos,
                    const float* __restrict__ Wpe, const float* __restrict__ bpe,
                    const float* __restrict__ Wq, const float* __restrict__ Wp) {
    __shared__ float rel[MB][3];
    int tid = threadIdx.x;
    if (blockIdx.x < 1024) {
        int i = blockIdx.x * 256 + tid;
        if (i < NQKV * DIMM) {
            int c = i >> 8, d = i & 255;
            int h = c / 96, t = c % 96, e = t / 3, s = t - e * 3;
            float v = Wq[i];
            int row = h * 32 + e;
            if (s == 0) {
                g_wq[row * DIMM + d] = v;
            } else {
                __nv_bfloat16 hh = __float2bfloat16(v);
                int brow = (s == 2) ? row : 256 + row;   // V rows 0-255, K rows 256-511
                g_wvkh[brow * DIMM + d] = hh;
                g_wvkl[brow * DIMM + d] = __float2bfloat16(v - __bfloat162float(hh));
                if (s == 1) g_wkt[d * 256 + row] = v;    // transposed for kmg
            }
        } else {
            int j = i - NQKV * DIMM;
            float v = Wp[j];
            __nv_bfloat16 hh = __float2bfloat16(v);
            g_wph[j] = hh;
            g_wpl[j] = __float2bfloat16(v - __bfloat162float(hh));
        }
        return;
    }
    int ball = blockIdx.x - 1024;
    if (tid < 3) {
        float s = 0.f;
        for (int m = 0; m < MB; m++) s += pos[(ball * MB + m) * 3 + tid];
        float mean = s * (1.f / MB);
        for (int m = 0; m < MB; m++)
            rel[m][tid] = pos[(ball * MB + m) * 3 + tid] - mean;
    }
    __syncthreads();
    int d = tid;
    float w0 = Wpe[d * 3 + 0], w1 = Wpe[d * 3 + 1], w2 = Wpe[d * 3 + 2];
    float b  = bpe[d];
    float xs = 0.f;
    #pragma unroll
    for (int m = 0; m < MB; m++) {
        int t = ball * MB + m;
        float v = x[t * DIMM + d]
                + rel[m][0] * w0 + rel[m][1] * w1 + rel[m][2] * w2 + b;
        g_xp[t * DIMM + d] = v;
        xs += v;
        __nv_bfloat16 h = __float2bfloat16(v);
        g_xph[t * DIMM + d] = h;
        g_xpl[t * DIMM + d] = __float2bfloat16(v - __bfloat162float(h));
    }
    g_xpm[ball * DIMM + d] = xs * (1.f / MB);
}

// ---------------- fp32 f32x2 GEMM-NT for Q: 64x128 tiles, 256 CTAs @2/SM ----------
__global__ void __launch_bounds__(256, 2)
k2_q(const float* __restrict__ bias) {
    __shared__ float As[2][16 * 68];
    __shared__ float Bs[2][16 * 132];
    int tid = threadIdx.x;
    int tx = tid & 15, ty = tid >> 4;
    int row0 = blockIdx.x * 64, col0 = blockIdx.y * 128;

    int ra  = tid & 63;
    int ka4 = (tid >> 6) * 4;
    int rb  = tid & 127;
    int kb8 = (tid >> 7) * 8;

    const float* Ap = g_xp + (row0 + ra) * DIMM + ka4;
    const float* Bp = g_wq + (col0 + rb) * DIMM + kb8;

    float4 pa  = *(const float4*)(Ap);
    float4 pb0 = *(const float4*)(Bp);
    float4 pb1 = *(const float4*)(Bp + 4);

    ull accp[4][4] = {};
    #pragma unroll 2
    for (int c = 0; c < 16; c++) {
        float* A = As[c & 1];
        float* B = Bs[c & 1];
        A[(ka4 + 0) * 68 + ra] = pa.x;
        A[(ka4 + 1) * 68 + ra] = pa.y;
        A[(ka4 + 2) * 68 + ra] = pa.z;
        A[(ka4 + 3) * 68 + ra] = pa.w;
        B[(kb8 + 0) * 132 + rb] = pb0.x; B[(kb8 + 1) * 132 + rb] = pb0.y;
        B[(kb8 + 2) * 132 + rb] = pb0.z; B[(kb8 + 3) * 132 + rb] = pb0.w;
        B[(kb8 + 4) * 132 + rb] = pb1.x; B[(kb8 + 5) * 132 + rb] = pb1.y;
        B[(kb8 + 6) * 132 + rb] = pb1.z; B[(kb8 + 7) * 132 + rb] = pb1.w;
        __syncthreads();
        if (c < 15) {
            int k0n = (c + 1) * 16;
            pa  = *(const float4*)(Ap + k0n);
            pb0 = *(const float4*)(Bp + k0n);
            pb1 = *(const float4*)(Bp + k0n + 4);
        }
        #pragma unroll
        for (int kk = 0; kk < 16; kk++) {
            float4 a  = *(const float4*)(A + kk * 68 + ty * 4);
            float4 b0 = *(const float4*)(B + kk * 132 + tx * 4);
            float4 b1 = *(const float4*)(B + kk * 132 + 64 + tx * 4);
            ull bp[4] = {pack2(b0.x, b0.y), pack2(b0.z, b0.w),
                         pack2(b1.x, b1.y), pack2(b1.z, b1.w)};
            float av[4] = {a.x, a.y, a.z, a.w};
            #pragma unroll
            for (int i = 0; i < 4; i++) {
                ull ap = pack2(av[i], av[i]);
                #pragma unroll
                for (int j = 0; j < 4; j++) accp[i][j] = fma2(ap, bp[j], accp[i][j]);
            }
        }
        __syncthreads();
    }
    float acc[4][8];
    #pragma unroll
    for (int i = 0; i < 4; i++)
        #pragma unroll
        for (int j = 0; j < 4; j++)
            unpack2(accp[i][j], acc[i][2 * j], acc[i][2 * j + 1]);
    #pragma unroll
    for (int i = 0; i < 4; i++) {
        int rr = row0 + ty * 4 + i;
        #pragma unroll
        for (int j = 0; j < 8; j++) {
            int cp = col0 + ((j < 4) ? tx * 4 + j : 64 + tx * 4 + j - 4);
            int h = cp >> 5, e = cp & 31;
            float v = acc[i][j] + bias[h * 96 + e * 3];
            int qi = (h * NM + rr) * EE + e;
            g_q[qi] = v;
            __nv_bfloat16 b1 = __float2bfloat16(v);
            float f1 = __bfloat162float(b1);
            __nv_bfloat16 b2 = __float2bfloat16(v - f1);
            float f2 = __bfloat162float(b2);
            __nv_bfloat16 b3 = __float2bfloat16(v - f1 - f2);
            g_q1[qi] = b1; g_q2[qi] = b2; g_q3[qi] = b3;
        }
    }
}

// ---------------- split-bf16 HMMA GEMM-NT, 128x128 tile, cp.async pipelined --------
// MODE 0: A=g_xph/l, B=g_wvkh/l (N=512: V cols 0-255, K cols 256-511).
// MODE 1: A=g_aoh/l, B=g_wph/l (N=256) -> out.
template<int MODE>
__device__ __forceinline__ void issue_chunk(uint32_t stage, int row0, int col0,
                                            int k0, int tid) {
    const __nv_bfloat16* srcs[4] = {
        (MODE == 0) ? g_xph : g_aoh, (MODE == 0) ? g_xpl : g_aol,
        (MODE == 0) ? g_wvkh : g_wph, (MODE == 0) ? g_wvkl : g_wpl};
    #pragma unroll
    for (int b = 0; b < 4; b++) {
        int rbase = (b < 2) ? row0 : col0;
        #pragma unroll
        for (int l = 0; l < 4; l++) {
            int u = tid + l * 256;
            int r = u >> 3, cc = u & 7;
            const void* g = srcs[b] + (rbase + r) * DIMM + k0 + cc * 8;
            uint32_t off = (uint32_t)(r * 128 + cc * 16);
            off ^= (off >> 3) & 0x70;
            cpasync16(stage + b * 16384 + off, g);
        }
    }
    asm volatile("cp.async.commit_group;" ::: "memory");
}

template<int MODE>
__global__ void __launch_bounds__(256, 1)
gemm_mma(const float* __restrict__ bias, float* __restrict__ out) {
    extern __shared__ char dsm_raw[];
    int tid = threadIdx.x;
    int wid = tid >> 5, lane = tid & 31;
    int row0 = blockIdx.x * 128, col0 = blockIdx.y * 128;
    int warp_m = (wid & 1) * 64;
    int warp_n = (wid >> 1) * 32;

    uint32_t raw = smem_u32(dsm_raw);
    uint32_t sbase = (raw + 1023u) & ~1023u;

    float acc[4][4][4] = {};
    int lr = lane & 7;
    int g  = lane >> 3;

    issue_chunk<MODE>(sbase, row0, col0, 0, tid);

    for (int chunk = 0; chunk < 4; chunk++) {
        if (chunk < 3)
            issue_chunk<MODE>(sbase + ((chunk + 1) & 1) * 65536,
                              row0, col0, (chunk + 1) * 64, tid);
        if (chunk < 3)
            asm volatile("cp.async.wait_group 1;" ::: "memory");
        else
            asm volatile("cp.async.wait_group 0;" ::: "memory");
        __syncthreads();

        uint32_t st = sbase + (chunk & 1) * 65536;
        uint32_t aBuf[2] = {st, st + 16384};
        uint32_t bBuf[2] = {st + 32768, st + 49152};

        #pragma unroll
        for (int pass = 0; pass < 3; pass++) {
            uint32_t abase = aBuf[(pass == 2) ? 1 : 0];
            uint32_t bbase = bBuf[(pass == 1) ? 1 : 0];
            #pragma unroll
            for (int ks = 0; ks < 4; ks++) {
                uint32_t af[4][4];
                #pragma unroll
                for (int mi = 0; mi < 4; mi++) {
                    int row = warp_m + mi * 16 + ((g & 1) << 3) + lr;
                    int cb  = ks * 32 + ((g >> 1) << 4);
                    ldsm4(af[mi][0], af[mi][1], af[mi][2], af[mi][3],
                          swz_addr(abase, row, cb));
                }
                uint32_t bf[4][2];
                #pragma unroll
                for (int p = 0; p < 2; p++) {
                    int n  = warp_n + p * 16 + ((g >> 1) << 3) + lr;
                    int cb = ks * 32 + ((g & 1) << 4);
                    uint32_t r0, r1, r2, r3;
                    ldsm4(r0, r1, r2, r3, swz_addr(bbase, n, cb));
                    bf[p * 2 + 0][0] = r0; bf[p * 2 + 0][1] = r1;
                    bf[p * 2 + 1][0] = r2; bf[p * 2 + 1][1] = r3;
                }
                #pragma unroll
                for (int mi = 0; mi < 4; mi++)
                    #pragma unroll
                    for (int nj = 0; nj < 4; nj++)
                        mma16816(acc[mi][nj], af[mi], bf[nj][0], bf[nj][1]);
            }
        }
        __syncthreads();
    }

    int erow = lane >> 2;
    int ecol = (lane & 3) * 2;
    #pragma unroll
    for (int mi = 0; mi < 4; mi++) {
        #pragma unroll
        for (int nj = 0; nj < 4; nj++) {
            #pragma unroll
            for (int half = 0; half < 2; half++) {
                int r = row0 + warp_m + mi * 16 + erow + half * 8;
                #pragma unroll
                for (int rg = 0; rg < 2; rg++) {
                    int cp = col0 + warp_n + nj * 8 + ecol + rg;
                    float a = acc[mi][nj][half * 2 + rg];
                    if (MODE == 0) {
                        if (cp < 256) {   // V
                            int h = cp >> 5, e = cp & 31;
                            float v = a + bias[h * 96 + e * 3 + 2];
                            g_vh[(h * NM + r) * EE + e] = __float2half(v);
                        } else {          // K
                            int m = cp - 256;
                            int h = m >> 5, e = m & 31;
                            float v = a + bias[h * 96 + e * 3 + 1];
                            g_kh[(h * NM + r) * EE + e] = __float2half(v);
                        }
                    } else {
                        out[r * DIMM + cp] = a + bias[cp];
                    }
                }
            }
        }
    }
}

// ---------------- kmg: kmean = xpm @ Wk^T + bk -- 512 CTAs, 8 d-slices --------------
// grid (64 ballgroups, 8 colgroups of 32); thread = (col in 32, d-slice in 8).
__global__ void __launch_bounds__(256)
kmg(const float* __restrict__ bias) {
    __shared__ float xm[8 * DIMM];              // 8 balls x 256
    __shared__ float part[8 * 8 * 32];          // [i][ds][col32]
    int b0 = blockIdx.x * 8;
    int cg = blockIdx.y;
    int tid = threadIdx.x;
    #pragma unroll
    for (int i = 0; i < 8; i++)
        xm[i * DIMM + tid] = g_xpm[(b0 + i) * DIMM + tid];
    __syncthreads();

    int c32 = tid & 31;
    int ds  = tid >> 5;                         // 0..7
    int col = cg * 32 + c32;
    float acc[8] = {};
    #pragma unroll 8
    for (int dd = 0; dd < 32; dd++) {
        int d = ds * 32 + dd;
        float w = g_wkt[d * 256 + col];         // 32 consecutive cols: coalesced
        #pragma unroll
        for (int i = 0; i < 8; i++) acc[i] += xm[i * DIMM + d] * w;
    }
    #pragma unroll
    for (int i = 0; i < 8; i++)
        part[(i * 8 + ds) * 32 + c32] = acc[i];
    __syncthreads();

    // 256 outputs per block (8 balls x 32 cols); one per thread
    {
        int i  = tid >> 5;
        int cc = tid & 31;
        float v = ((part[(i * 8 + 0) * 32 + cc] + part[(i * 8 + 1) * 32 + cc])
                 + (part[(i * 8 + 2) * 32 + cc] + part[(i * 8 + 3) * 32 + cc]))
                + ((part[(i * 8 + 4) * 32 + cc] + part[(i * 8 + 5) * 32 + cc])
                 + (part[(i * 8 + 6) * 32 + cc] + part[(i * 8 + 7) * 32 + cc]));
        int colo = cg * 32 + cc;
        int h = colo >> 5, e = colo & 31;
        v += bias[h * 96 + e * 3 + 1];
        int t = (h * NB + b0 + i) * EE + e;
        __nv_bfloat16 b1 = __float2bfloat16(v);
        float f1 = __bfloat162float(b1);
        __nv_bfloat16 b2 = __float2bfloat16(v - f1);
        float f2 = __bfloat162float(b2);
        __nv_bfloat16 b3 = __float2bfloat16(v - f1 - f2);
        g_km1[t] = b1; g_km2[t] = b2; g_km3[t] = b3;
    }
}

// ---------------- k4: sim via HMMA, 32 tok/warp, 4 chains, B prefetch ---------------
__device__ __forceinline__ void k4_load_b(uint32_t bfr[3][2][2], int h, int ball0,
                                          int mrow, int ep) {
    const __nv_bfloat16* ms[3] = {g_km1, g_km2, g_km3};
    #pragma unroll
    for (int s = 0; s < 3; s++) {
        const __nv_bfloat16* m = ms[s] + (h * NB + ball0 + mrow) * EE;
        #pragma unroll
        for (int kk = 0; kk < 2; kk++) {
            int e = kk * 16 + ep;
            bfr[s][kk][0] = *(const uint32_t*)(m + e);
            bfr[s][kk][1] = *(const uint32_t*)(m + e + 8);
        }
    }
}

__device__ __forceinline__ void top2_merge(float& v1, float& v2, int& i1, int& i2,
                                           float s, int c) {
    if (s > v1) { v2 = v1; i2 = i1; v1 = s; i1 = c; }
    else if (s > v2) { v2 = s; i2 = c; }
}

__global__ void __launch_bounds__(256, 2)
k4_top2() {
    int h = blockIdx.y;
    int tid = threadIdx.x;
    int wid = tid >> 5, lane = tid & 31;
    int tokw = blockIdx.x * 256 + wid * 32;
    int mrow = lane >> 2;
    int ep   = (lane & 3) * 2;

    const __nv_bfloat16* qs[3] = {g_q1, g_q2, g_q3};

    uint32_t afr[2][3][2][4];
    #pragma unroll
    for (int m = 0; m < 2; m++) {
        #pragma unroll
        for (int s = 0; s < 3; s++) {
            const __nv_bfloat16* q = qs[s] + (h * NM + tokw + m * 16) * EE;
            #pragma unroll
            for (int kk = 0; kk < 2; kk++) {
                int e = kk * 16 + ep;
                afr[m][s][kk][0] = *(const uint32_t*)(q + (mrow    ) * EE + e);
                afr[m][s][kk][1] = *(const uint32_t*)(q + (mrow + 8) * EE + e);
                afr[m][s][kk][2] = *(const uint32_t*)(q + (mrow    ) * EE + e + 8);
                afr[m][s][kk][3] = *(const uint32_t*)(q + (mrow + 8) * EE + e + 8);
            }
        }
    }

    float v1[4], v2[4];
    int   i1[4], i2[4];
    #pragma unroll
    for (int r = 0; r < 4; r++) { v1[r] = -1e30f; v2[r] = -1e30f; i1[r] = 0; i2[r] = 0; }

    uint32_t bf[2][3][2][2];
    k4_load_b(bf[0], h, 0, mrow, ep);

    #pragma unroll 2
    for (int grp = 0; grp < 64; grp++) {
        int cur = grp & 1;
        int ball0 = grp * 8;
        if (grp < 63)
            k4_load_b(bf[cur ^ 1], h, ball0 + 8, mrow, ep);

        float ac[4][4] = {};
        #pragma unroll
        for (int kk = 0; kk < 2; kk++) {
            uint32_t b00 = bf[cur][0][kk][0], b01 = bf[cur][0][kk][1];
            uint32_t b10 = bf[cur][1][kk][0], b11 = bf[cur][1][kk][1];
            uint32_t b20 = bf[cur][2][kk][0], b21 = bf[cur][2][kk][1];
            mma16816(ac[0], afr[0][0][kk], b00, b01);
            mma16816(ac[2], afr[1][0][kk], b00, b01);
            mma16816(ac[1], afr[0][0][kk], b10, b11);
            mma16816(ac[3], afr[1][0][kk], b10, b11);
            mma16816(ac[0], afr[0][1][kk], b00, b01);
            mma16816(ac[2], afr[1][1][kk], b00, b01);
            mma16816(ac[1], afr[0][1][kk], b10, b11);
            mma16816(ac[3], afr[1][1][kk], b10, b11);
            mma16816(ac[0], afr[0][0][kk], b20, b21);
            mma16816(ac[2], afr[1][0][kk], b20, b21);
            mma16816(ac[1], afr[0][2][kk], b00, b01);
            mma16816(ac[3], afr[1][2][kk], b00, b01);
        }

        int c0 = ball0 + ep, c1 = c0 + 1;
        #pragma unroll
        for (int m = 0; m < 2; m++) {
            float s0 = ac[2 * m][0] + ac[2 * m + 1][0];
            float s1 = ac[2 * m][1] + ac[2 * m + 1][1];
            float s2 = ac[2 * m][2] + ac[2 * m + 1][2];
            float s3 = ac[2 * m][3] + ac[2 * m + 1][3];
            int ra = m * 2, rb = m * 2 + 1;
            top2_merge(v1[ra], v2[ra], i1[ra], i2[ra], s0, c0);
            top2_merge(v1[ra], v2[ra], i1[ra], i2[ra], s1, c1);
            top2_merge(v1[rb], v2[rb], i1[rb], i2[rb], s2, c0);
            top2_merge(v1[rb], v2[rb], i1[rb], i2[rb], s3, c1);
        }
    }

    #pragma unroll
    for (int r = 0; r < 4; r++) {
        float a1 = v1[r], a2 = v2[r];
        int   b1 = i1[r], b2 = i2[r];
        #pragma unroll
        for (int d = 1; d < 4; d <<= 1) {
            float o1 = __shfl_xor_sync(0xffffffffu, a1, d);
            float o2 = __shfl_xor_sync(0xffffffffu, a2, d);
            int  oi1 = __shfl_xor_sync(0xffffffffu, b1, d);
            int  oi2 = __shfl_xor_sync(0xffffffffu, b2, d);
            if (o1 > a1) {
                if (a1 > o2) { a2 = a1; b2 = b1; } else { a2 = o2; b2 = oi2; }
                a1 = o1; b1 = oi1;
            } else if (o1 > a2) { a2 = o1; b2 = oi1; }
        }
        if ((lane & 3) == 0) {
            int tok = h * NM + tokw + (r >> 1) * 16 + (r & 1) * 8 + mrow;
            g_idx[tok * 2 + 0] = b1;
            g_idx[tok * 2 + 1] = b2;
        }
    }
}

// ---------------- k5: gathered 32-key attention (fp16 K,V) + bf16 split out ---------
__global__ void k5_attn() {
    int warp = (blockIdx.x * blockDim.x + threadIdx.x) >> 5;
    int lane = threadIdx.x & 31;
    int h = warp >> 13;
    int tok = warp & (NM - 1);
    int b0 = g_idx[warp * 2 + 0];
    int b1 = g_idx[warp * 2 + 1];

    int ball = (lane < 16) ? b0 : b1;
    int ktok = ball * MB + (lane & 15);
    const uint4*  kr4  = (const uint4*)(g_kh + (h * NM + ktok) * EE);
    const float4* qrow = (const float4*)(g_q + (h * NM + tok) * EE);
    float logit = 0.f;
    #pragma unroll
    for (int i = 0; i < 4; i++) {
        uint4 u = kr4[i];
        float4 qa = qrow[2 * i], qb = qrow[2 * i + 1];
        float2 k0 = __half22float2(*(__half2*)&u.x);
        float2 k1 = __half22float2(*(__half2*)&u.y);
        float2 k2 = __half22float2(*(__half2*)&u.z);
        float2 k3 = __half22float2(*(__half2*)&u.w);
        logit += qa.x * k0.x + qa.y * k0.y + qa.z * k1.x + qa.w * k1.y
               + qb.x * k2.x + qb.y * k2.y + qb.z * k3.x + qb.w * k3.y;
    }
    logit *= 0.17677669529663688f;

    float m = logit;
    #pragma unroll
    for (int off = 16; off > 0; off >>= 1)
        m = fmaxf(m, __shfl_xor_sync(0xffffffffu, m, off));
    float p = __expf(logit - m);
    float s = p;
    #pragma unroll
    for (int off = 16; off > 0; off >>= 1)
        s += __shfl_xor_sync(0xffffffffu, s, off);
    float attn = p / s;

    float out = 0.f;
    #pragma unroll
    for (int kk = 0; kk < NKEY; kk++) {
        float a = __shfl_sync(0xffffffffu, attn, kk);
        int kt = ((kk < 16) ? b0 : b1) * MB + (kk & 15);
        out += a * __half2float(g_vh[(h * NM + kt) * EE + lane]);
    }
    int oi = tok * DIMM + h * EE + lane;
    __nv_bfloat16 hi = __float2bfloat16(out);
    g_aoh[oi] = hi;
    g_aol[oi] = __float2bfloat16(out - __bfloat162float(hi));
}

// ---------------- launch --------------------------------------------------------------
extern "C" void kernel_launch(void* const* d_in, const int* in_sizes, int n_in,
                              void* d_out, int out_size) {
    const float* x     = (const float*)d_in[0];
    const float* pos   = (const float*)d_in[1];
    const float* Wqkv  = (const float*)d_in[2];
    const float* bqkv  = (const float*)d_in[3];
    const float* Wpe   = (const float*)d_in[4];
    const float* bpe   = (const float*)d_in[5];
    const float* Wproj = (const float*)d_in[6];
    const float* bproj = (const float*)d_in[7];
    float* out = (float*)d_out;

    const int DSMEM = 2 * 65536 + 1024;
    cudaFuncSetAttribute(gemm_mma<0>, cudaFuncAttributeMaxDynamicSharedMemorySize, DSMEM);
    cudaFuncSetAttribute(gemm_mma<1>, cudaFuncAttributeMaxDynamicSharedMemorySize, DSMEM);

    k01<<<1024 + NB, 256>>>(x, pos, Wpe, bpe, Wqkv, Wproj);
    k2_q<<<dim3(NM / 64, 2), 256>>>(bqkv);
    gemm_mma<0><<<dim3(NM / 128, 4), 256, DSMEM>>>(bqkv, nullptr);
    kmg<<<dim3(NB / 8, 8), 256>>>(bqkv);
    k4_top2<<<dim3(NM / 256, NH), 256>>>();
    k5_attn<<<(NH * NM * 32) / 256, 256>>>();
    gemm_mma<1><<<dim3(NM / 128, DIMM / 128), 256, DSMEM>>>(bproj, out);
}